// round 11
// baseline (speedup 1.0000x reference)
#include <cuda_runtime.h>
#include <cuda_fp16.h>
#include <cstdint>

#define NB 8
#define NN 2048
#define HH 512
#define MROWS (NB * NN)   // 16384

// ---------------------------------------------------------------------------
// Scratch (device globals — no allocation allowed)
// ---------------------------------------------------------------------------
__device__ float  g_x[MROWS * HH];                 // residual x (fp32)
__device__ __half g_xr[MROWS * HH];                // fp16 copy of x
__device__ float  g_h[MROWS * 1024];               // fp32 activations (layer-2 only)
__device__ __half g_hr[MROWS * 1024];              // fp16 activations
__device__ __half g_hwt[(size_t)1024 * MROWS];     // (h @ W)^T [Fo][MROWS], fp16
__device__ __half g_P[(size_t)MROWS * NN];         // unnormalized attention, fp16 (L1/L2)
__device__ __half g_wt[1024 * 1024];               // W^T [N][K], fp16
__device__ uint32_t g_adjT[MROWS * (NN / 32)];     // bit: valid(t, s), self-loop folded
__device__ float  g_ee[2 * MROWS];                 // [0..M) esrc, [M..2M) edst
__device__ float  g_f1[MROWS], g_f2[MROWS];        // per-source exp factors
__device__ float  g_qa[MROWS], g_qb[MROWS];        // per-target exp factors
__device__ float  g_rz[MROWS];                     // 1 / row-sum of P'
__device__ unsigned int g_smax_bits[NB];           // orderable-int max of esrc per batch
__device__ float  g_Weff[6 * HH];
__device__ float  g_beff[HH];
// Layer-0 rank-6 path
__device__ float  g_feats[MROWS * 8];              // 6 features, padded to 8
__device__ float  g_c6[MROWS * 8];                 // P-hat @ feats (rz-scaled), padded
__device__ float  g_W0eff[6 * 1024];               // Weff @ W0
__device__ float  g_b0w[1024];                     // beff @ W0
__device__ float  g_b0eff[1024];                   // beff @ W0 + gat_b0
__device__ float  g_v6[14];                        // [0..6) vsrc6, [6..12) vdst6, [12] c_src, [13] c_dst

// ---------------------------------------------------------------------------
// Helpers
// ---------------------------------------------------------------------------
__device__ __forceinline__ unsigned enc_ord(float f) {
    unsigned i = __float_as_uint(f);
    return (i & 0x80000000u) ? ~i : (i | 0x80000000u);
}
__device__ __forceinline__ float dec_ord(unsigned k) {
    unsigned i = (k & 0x80000000u) ? (k & 0x7FFFFFFFu) : ~k;
    return __uint_as_float(i);
}
__device__ __forceinline__ uint32_t smem_u32(const void* p) {
    uint32_t a;
    asm("{ .reg .u64 t; cvta.to.shared.u64 t, %1; cvt.u32.u64 %0, t; }" : "=r"(a) : "l"(p));
    return a;
}
__device__ __forceinline__ void mma16(float* c, const uint32_t* a, const uint32_t* b) {
    asm volatile(
        "mma.sync.aligned.m16n8k16.row.col.f32.f16.f16.f32 "
        "{%0,%1,%2,%3}, {%4,%5,%6,%7}, {%8,%9}, {%0,%1,%2,%3};"
        : "+f"(c[0]), "+f"(c[1]), "+f"(c[2]), "+f"(c[3])
        : "r"(a[0]), "r"(a[1]), "r"(a[2]), "r"(a[3]), "r"(b[0]), "r"(b[1]));
}
__device__ __forceinline__ void ldsm4(uint32_t* r, uint32_t addr) {
    asm volatile("ldmatrix.sync.aligned.m8n8.x4.shared.b16 {%0,%1,%2,%3}, [%4];"
                 : "=r"(r[0]), "=r"(r[1]), "=r"(r[2]), "=r"(r[3]) : "r"(addr));
}
#define CPA(dst, src) asm volatile("cp.async.cg.shared.global [%0], [%1], 16;" :: "r"(dst), "l"(src))
#define CPC() asm volatile("cp.async.commit_group;")
#define CPW(n) asm volatile("cp.async.wait_group %0;" :: "n"(n))

// k-major fp16 tile: 128 rows x 64 halfs (128 bytes/row). 16B chunk c4k = 0..7.
#define SOFFB(row, c4k) ((row) * 128 + ((((c4k)) ^ ((row) & 7)) << 4))

#define STAGE_BYTES 32768                 // A 16KB + B 16KB per stage (kt = 64)
#define SMEM_BYTES (3 * STAGE_BYTES)      // 96 KB, 2 CTAs/SM

// ---------------------------------------------------------------------------
// Unified fp16 tensor-core GEMM (fp32 accumulate). Same as R10.
// EPI 0: Ch^T[n][m] = h(acc); fused esrc/edst dots
// EPI 1: Ch = h(relu(acc*rz + bias))               (attention mid, batched)
// EPI 2: C = acc*rz + bias + X; Ch = h(C)          (attention last, batched)
// EPI 3: C = X + relu(acc + bias); Ch = h(C)       (ff1)
// EPI 4: C = (X + relu(acc + bias)) * act[row]     (ff2)
// ---------------------------------------------------------------------------
template <int EPI>
__global__ __launch_bounds__(256, 2) void gemm_tc(
    const __half* __restrict__ A, const __half* __restrict__ Bt,
    float* __restrict__ C, __half* __restrict__ Ch, int K, int N,
    const float* __restrict__ bias, const float* __restrict__ X,
    const float* __restrict__ act, const float* __restrict__ rz,
    float* __restrict__ ee)
{
    constexpr bool BATCHED = (EPI == 1 || EPI == 2);
    extern __shared__ char smc[];
    const uint32_t sbase = smem_u32(smc);
    const int tid = threadIdx.x;
    const int lane = tid & 31, wid = tid >> 5;

    int bx = blockIdx.x, by = blockIdx.y;
    {
        const int GX = gridDim.x;
        const int lin = by * GX + bx;
        const int grp = lin / (4 * GX);
        const int rem = lin - grp * 4 * GX;
        by = grp * 4 + (rem & 3);
        bx = rem >> 2;
    }
    const int m0 = by * 128, n0 = bx * 128;
    const int ws = wid >> 2, wcs = wid & 3;
    const int wm = ws * 64, wn = wcs * 32;

    int zoff = 0;
    if (BATCHED) zoff = blockIdx.z * NN;
    const __half* Ab = A + (size_t)zoff * K;
    const int ldb = BATCHED ? MROWS : K;
    const int kboff = BATCHED ? zoff : 0;
    float* Cb = (C != nullptr) ? C + (size_t)zoff * N : nullptr;
    __half* Chb = (Ch != nullptr && EPI != 0) ? Ch + (size_t)zoff * N : Ch;
    const float* Xb = (EPI >= 2) ? X + (size_t)zoff * N : nullptr;
    const float* rzb = BATCHED ? rz + zoff : nullptr;

    float acc[4][4][4];
#pragma unroll
    for (int i = 0; i < 4; i++)
#pragma unroll
        for (int j = 0; j < 4; j++)
#pragma unroll
            for (int q = 0; q < 4; q++) acc[i][j][q] = 0.f;

    const int row_l = tid >> 3, c4_l = tid & 7;

    auto issue = [&](int kt) {
        const int k0 = kt << 6;
        const uint32_t aB = sbase + (kt % 3) * STAGE_BYTES;
        const uint32_t bB = aB + 16384;
#pragma unroll
        for (int p = 0; p < 4; p++) {
            const int row = row_l + p * 32;
            const uint32_t so = SOFFB(row, c4_l);
            CPA(aB + so, Ab + (size_t)(m0 + row) * K + k0 + c4_l * 8);
            CPA(bB + so, Bt + (size_t)(n0 + row) * ldb + kboff + k0 + c4_l * 8);
        }
        CPC();
    };

    const int mA_row = lane & 15, mA_k = lane >> 4;
    const int nB_row = (lane & 7) + ((lane >> 4) << 3);
    const int nB_k = (lane >> 3) & 1;

    auto compute = [&](int stg) {
        const uint32_t aB = sbase + stg * STAGE_BYTES;
        const uint32_t bB = aB + 16384;
#pragma unroll
        for (int kk = 0; kk < 4; kk++) {
            uint32_t fa[4][4], fb[2][4];
#pragma unroll
            for (int mf = 0; mf < 4; mf++)
                ldsm4(fa[mf], aB + SOFFB(wm + mf * 16 + mA_row, kk * 2 + mA_k));
#pragma unroll
            for (int bp = 0; bp < 2; bp++)
                ldsm4(fb[bp], bB + SOFFB(wn + bp * 16 + nB_row, kk * 2 + nB_k));
#pragma unroll
            for (int mf = 0; mf < 4; mf++)
#pragma unroll
                for (int nf = 0; nf < 4; nf++)
                    mma16(acc[mf][nf], fa[mf], &fb[nf >> 1][(nf & 1) * 2]);
        }
    };

    const int nkt = K >> 6;
    issue(0);
    issue(1);
    for (int kt = 0; kt < nkt; kt++) {
        if (kt < nkt - 1) { CPW(1); } else { CPW(0); }
        __syncthreads();
        if (kt + 2 < nkt) issue(kt + 2);
        compute(kt % 3);
    }

#pragma unroll
    for (int mf = 0; mf < 4; mf++) {
#pragma unroll
        for (int rr = 0; rr < 2; rr++) {
            const int r = m0 + wm + mf * 16 + (lane >> 2) + rr * 8;
            float rzv = 1.f, actv = 1.f;
            if (BATCHED) rzv = rzb[r];
            if (EPI == 4) actv = act[r];
            float sE = 0.f, sD = 0.f;
#pragma unroll
            for (int nf = 0; nf < 4; nf++) {
                const int cc = n0 + wn + nf * 8 + (lane & 3) * 2;
                float v0 = acc[mf][nf][rr * 2 + 0];
                float v1 = acc[mf][nf][rr * 2 + 1];
                if (EPI == 0) {
                    const __half h0 = __float2half_rn(v0);
                    const __half h1 = __float2half_rn(v1);
                    Ch[(size_t)cc * MROWS + r]       = h0;
                    Ch[(size_t)(cc + 1) * MROWS + r] = h1;
                    const float c0 = __half2float(h0), c1 = __half2float(h1);
                    sE += c0 * bias[cc] + c1 * bias[cc + 1];
                    sD += c0 * X[cc] + c1 * X[cc + 1];
                } else {
                    if (BATCHED) { v0 *= rzv; v1 *= rzv; }
                    v0 += bias[cc]; v1 += bias[cc + 1];
                    if (EPI == 1) {
                        v0 = fmaxf(v0, 0.f); v1 = fmaxf(v1, 0.f);
                        *reinterpret_cast<__half2*>(Chb + (size_t)r * N + cc) =
                            __floats2half2_rn(v0, v1);
                    } else {
                        if (EPI == 2) {
                            const float* xr = Xb + (size_t)r * N + cc;
                            v0 += xr[0]; v1 += xr[1];
                        } else if (EPI == 3) {
                            const float* xr = Xb + (size_t)r * N + cc;
                            v0 = xr[0] + fmaxf(v0, 0.f); v1 = xr[1] + fmaxf(v1, 0.f);
                        } else if (EPI == 4) {
                            const float* xr = Xb + (size_t)r * N + cc;
                            v0 = (xr[0] + fmaxf(v0, 0.f)) * actv;
                            v1 = (xr[1] + fmaxf(v1, 0.f)) * actv;
                        }
                        *reinterpret_cast<float2*>(Cb + (size_t)r * N + cc) = make_float2(v0, v1);
                        if (EPI == 2 || EPI == 3) {
                            *reinterpret_cast<__half2*>(Chb + (size_t)r * N + cc) =
                                __floats2half2_rn(v0, v1);
                        }
                    }
                }
            }
            if (EPI == 0) {
                sE += __shfl_xor_sync(0xFFFFFFFFu, sE, 1);
                sE += __shfl_xor_sync(0xFFFFFFFFu, sE, 2);
                sD += __shfl_xor_sync(0xFFFFFFFFu, sD, 1);
                sD += __shfl_xor_sync(0xFFFFFFFFu, sD, 2);
                if ((lane & 3) == 0) {
                    atomicAdd(ee + r, sE);
                    atomicAdd(ee + MROWS + r, sD);
                }
            }
        }
    }
}

// ---------------------------------------------------------------------------
// 32x32 tiled transpose to fp16
// ---------------------------------------------------------------------------
__global__ void transpose_kernel(const float* __restrict__ in, __half* __restrict__ out,
                                 int R, int Cc)
{
    __shared__ float tile[32][33];
    int c0 = blockIdx.x * 32, r0 = blockIdx.y * 32;
    int x = threadIdx.x, y = threadIdx.y;
#pragma unroll
    for (int i = 0; i < 32; i += 8)
        tile[y + i][x] = in[(size_t)(r0 + y + i) * Cc + c0 + x];
    __syncthreads();
#pragma unroll
    for (int i = 0; i < 32; i += 8)
        out[(size_t)(c0 + y + i) * R + r0 + x] = __float2half_rn(tile[x][y + i]);
}

// ---------------------------------------------------------------------------
// adjT: bit s of word (b,t,s/32) = (adj[b][s][t]!=0) | (s==t)
// ---------------------------------------------------------------------------
__global__ __launch_bounds__(1024) void adjT_kernel(const int* __restrict__ adj)
{
    __shared__ int sa[32][33];
    const int b = blockIdx.z, t0 = blockIdx.y * 32, s0 = blockIdx.x * 32;
    const int w = threadIdx.x >> 5, lane = threadIdx.x & 31;
    sa[w][lane] = adj[((size_t)b * NN + s0 + w) * NN + t0 + lane];
    __syncthreads();
    const int t = t0 + w;
    uint32_t word = __ballot_sync(0xFFFFFFFFu, sa[lane][w] != 0);
    if (lane == 0) {
        if ((t >> 5) == (s0 >> 5)) word |= 1u << (t & 31);
        g_adjT[((size_t)b * NN + t) * (NN / 32) + (s0 >> 5)] = word;
    }
}

// ---------------------------------------------------------------------------
// Weff = emb_W1 @ emb_W2 ; beff = emb_b1 @ emb_W2 + emb_b2
// ---------------------------------------------------------------------------
__global__ void prep_weff_kernel(const float* __restrict__ W1, const float* __restrict__ b1,
                                 const float* __restrict__ W2, const float* __restrict__ b2)
{
    int j = blockIdx.x * 256 + threadIdx.x;
    if (j >= HH) return;
    float acc[6] = {0.f, 0.f, 0.f, 0.f, 0.f, 0.f};
    float bacc = b2[j];
    for (int k = 0; k < HH; k++) {
        float w2 = W2[k * HH + j];
        bacc += b1[k] * w2;
#pragma unroll
        for (int i = 0; i < 6; i++) acc[i] += W1[i * HH + k] * w2;
    }
#pragma unroll
    for (int i = 0; i < 6; i++) g_Weff[i * HH + j] = acc[i];
    g_beff[j] = bacc;
}

// ---------------------------------------------------------------------------
// W0eff = Weff @ W0 [6x1024]; b0w = beff @ W0; b0eff = b0w + gat_b0
// ---------------------------------------------------------------------------
__global__ void prep_l0a_kernel(const float* __restrict__ W0, const float* __restrict__ b0)
{
    int j = blockIdx.x * 256 + threadIdx.x;
    if (j >= 1024) return;
    float acc[6] = {0.f, 0.f, 0.f, 0.f, 0.f, 0.f};
    float bw = 0.f;
    for (int k = 0; k < HH; k++) {
        float w0 = W0[(size_t)k * 1024 + j];
        bw += g_beff[k] * w0;
#pragma unroll
        for (int i = 0; i < 6; i++) acc[i] += g_Weff[i * HH + k] * w0;
    }
#pragma unroll
    for (int i = 0; i < 6; i++) g_W0eff[i * 1024 + j] = acc[i];
    g_b0w[j] = bw;
    g_b0eff[j] = bw + b0[j];
}

// ---------------------------------------------------------------------------
// vsrc6[i] = W0eff[i]·a_src; vdst6[i] = W0eff[i]·a_dst; c_src = b0w·a_src; c_dst
// ---------------------------------------------------------------------------
__global__ __launch_bounds__(256) void prep_l0b_kernel(const float* __restrict__ asrc,
                                                       const float* __restrict__ adst)
{
    __shared__ float red[14][256];
    const int t = threadIdx.x;
    float p[14];
#pragma unroll
    for (int q = 0; q < 14; q++) p[q] = 0.f;
    for (int j = t; j < 1024; j += 256) {
        float as = asrc[j], ad = adst[j], bw = g_b0w[j];
#pragma unroll
        for (int i = 0; i < 6; i++) {
            float w = g_W0eff[i * 1024 + j];
            p[i] += w * as;
            p[6 + i] += w * ad;
        }
        p[12] += bw * as;
        p[13] += bw * ad;
    }
#pragma unroll
    for (int q = 0; q < 14; q++) red[q][t] = p[q];
    __syncthreads();
    for (int s = 128; s; s >>= 1) {
        if (t < s) {
#pragma unroll
            for (int q = 0; q < 14; q++) red[q][t] += red[q][t + s];
        }
        __syncthreads();
    }
    if (t < 14) g_v6[t] = red[t][0];
}

// ---------------------------------------------------------------------------
// Features (fp32, padded to 8) per row
// ---------------------------------------------------------------------------
__global__ void feats_kernel(const float* __restrict__ arr, const float* __restrict__ dep,
                             const float* __restrict__ hard,
                             const float* __restrict__ ts, const float* __restrict__ tt)
{
    int row = blockIdx.x * 256 + threadIdx.x;
    int b = row >> 11;
    float t = ts[b], T = tt[b];
    float ar = arr[row], de = dep[row];
    float* f = g_feats + row * 8;
    f[0] = (t - ar) / (de - ar);
    f[1] = t / T;
    f[2] = fmodf(f[1], 2.f);
    f[3] = fmodf(f[1], 4.f);
    f[4] = fmodf(f[1], 7.f);
    f[5] = hard[row];
    f[6] = 0.f; f[7] = 0.f;
}

// ---------------------------------------------------------------------------
// Feature construction + fused 6->512 embedding; writes x (fp32) and xr (fp16)
// ---------------------------------------------------------------------------
__global__ void embed_kernel(const float* __restrict__ arr, const float* __restrict__ dep,
                             const float* __restrict__ hard,
                             const float* __restrict__ ts, const float* __restrict__ tt)
{
    int idx = blockIdx.x * 256 + threadIdx.x;
    int j = idx & (HH - 1);
    int row = idx >> 9;
    int b = row >> 11;
    float t = ts[b], T = tt[b];
    float ar = arr[row], de = dep[row];
    float f[6];
    f[0] = (t - ar) / (de - ar);
    f[1] = t / T;
    f[2] = fmodf(f[1], 2.f);
    f[3] = fmodf(f[1], 4.f);
    f[4] = fmodf(f[1], 7.f);
    f[5] = hard[row];
    float acc = g_beff[j];
#pragma unroll
    for (int i = 0; i < 6; i++) acc += f[i] * g_Weff[i * HH + j];
    g_x[idx] = acc;
    g_xr[idx] = __float2half_rn(acc);
}

// ---------------------------------------------------------------------------
// Layer-0 e_src/e_dst via rank-6: e = feats·v6 + const
// ---------------------------------------------------------------------------
__global__ void l0_e_kernel()
{
    int row = blockIdx.x * 256 + threadIdx.x;
    const float* f = g_feats + row * 8;
    float es = g_v6[12], ed = g_v6[13];
#pragma unroll
    for (int i = 0; i < 6; i++) {
        es += f[i] * g_v6[i];
        ed += f[i] * g_v6[6 + i];
    }
    g_ee[row] = es;
    g_ee[MROWS + row] = ed;
}

// ---------------------------------------------------------------------------
// Zero e-accumulators + reset per-batch smax
// ---------------------------------------------------------------------------
__global__ void zero_ee2_kernel()
{
    int i = blockIdx.x * 256 + threadIdx.x;
    if (i < 2 * MROWS) g_ee[i] = 0.f;
    if (i < NB) g_smax_bits[i] = 0x007FFFFFu;  // enc(-inf)
}

// ---------------------------------------------------------------------------
// Per-batch max of esrc -> g_smax_bits
// ---------------------------------------------------------------------------
__global__ __launch_bounds__(256) void smax_kernel()
{
    const int i = blockIdx.x * 256 + threadIdx.x;
    float v = g_ee[i];
#pragma unroll
    for (int off = 16; off; off >>= 1)
        v = fmaxf(v, __shfl_xor_sync(0xFFFFFFFFu, v, off));
    __shared__ float red[8];
    const int w = threadIdx.x >> 5, l = threadIdx.x & 31;
    if (l == 0) red[w] = v;
    __syncthreads();
    if (threadIdx.x == 0) {
        float m = red[0];
#pragma unroll
        for (int q = 1; q < 8; q++) m = fmaxf(m, red[q]);
        atomicMax(&g_smax_bits[i >> 11], enc_ord(m));
    }
}

// ---------------------------------------------------------------------------
// Per-node exp factors (all exponents <= 0 -> no overflow)
// ---------------------------------------------------------------------------
__global__ void nodeprep_kernel()
{
    int t = blockIdx.x * 256 + threadIdx.x;
    int b = t >> 11;
    float sm = dec_ord(g_smax_bits[b]);
    float es = g_ee[t], ed = g_ee[MROWS + t];
    g_f1[t] = __expf(es - sm);
    g_f2[t] = __expf(0.2f * (es - sm));
    float u = ed + sm;
    float mh = fmaxf(u, 0.2f * u);
    g_qa[t] = __expf(u - mh);
    g_qb[t] = __expf(0.2f * u - mh);
}

// ---------------------------------------------------------------------------
// L0 fused pgen: generate P row in registers, accumulate Z and P@feats (6-wide).
// One warp per row; feats for the whole batch staged in smem. No P store.
// ---------------------------------------------------------------------------
__global__ __launch_bounds__(256) void pgen_l0_kernel()
{
    extern __shared__ float sf[];   // [2048][8] feats for this block's batch
    const int tid = threadIdx.x;
    const int wid = tid >> 5, lane = tid & 31;
    const int t = blockIdx.x * 8 + wid;
    const int b = t >> 11;
    // cooperative load of batch feats (16384 floats = 4096 float4)
    {
        const float4* src = reinterpret_cast<const float4*>(g_feats + (size_t)b * NN * 8);
        float4* dst = reinterpret_cast<float4*>(sf);
        for (int i = tid; i < 4096; i += 256) dst[i] = src[i];
    }
    __syncthreads();

    const float qa = g_qa[t], qb = g_qb[t];
    const uint32_t* wrow = g_adjT + (size_t)t * (NN / 32);
    const float* f1 = g_f1 + b * NN;
    const float* f2 = g_f2 + b * NN;
    float sum = 0.f;
    float c[6] = {0.f, 0.f, 0.f, 0.f, 0.f, 0.f};
#pragma unroll 2
    for (int i = 0; i < 16; i++) {
        const int s = i * 128 + lane * 4;
        const uint32_t w = wrow[s >> 5];
        const uint32_t sh = s & 31;
        float4 x1 = *reinterpret_cast<const float4*>(f1 + s);
        float4 x2 = *reinterpret_cast<const float4*>(f2 + s);
        float o[4];
        o[0] = ((w >> (sh + 0)) & 1u) ? fmaxf(qa * x1.x, qb * x2.x) : 0.f;
        o[1] = ((w >> (sh + 1)) & 1u) ? fmaxf(qa * x1.y, qb * x2.y) : 0.f;
        o[2] = ((w >> (sh + 2)) & 1u) ? fmaxf(qa * x1.z, qb * x2.z) : 0.f;
        o[3] = ((w >> (sh + 3)) & 1u) ? fmaxf(qa * x1.w, qb * x2.w) : 0.f;
#pragma unroll
        for (int j = 0; j < 4; j++) {
            sum += o[j];
            const float4 fa = *reinterpret_cast<const float4*>(sf + (s + j) * 8);
            const float2 fbv = *reinterpret_cast<const float2*>(sf + (s + j) * 8 + 4);
            c[0] += o[j] * fa.x; c[1] += o[j] * fa.y; c[2] += o[j] * fa.z;
            c[3] += o[j] * fa.w; c[4] += o[j] * fbv.x; c[5] += o[j] * fbv.y;
        }
    }
#pragma unroll
    for (int off = 16; off; off >>= 1) {
        sum += __shfl_xor_sync(0xFFFFFFFFu, sum, off);
#pragma unroll
        for (int q = 0; q < 6; q++) c[q] += __shfl_xor_sync(0xFFFFFFFFu, c[q], off);
    }
    if (lane == 0) {
        const float rzv = 1.f / fmaxf(sum, 1e-30f);
        g_rz[t] = rzv;
        float* co = g_c6 + t * 8;
#pragma unroll
        for (int q = 0; q < 6; q++) co[q] = c[q] * rzv;
    }
}

// ---------------------------------------------------------------------------
// L0 output: hr[t][j] = h(relu( c6[t]·W0eff[:,j] + b0eff[j] ))
// ---------------------------------------------------------------------------
__global__ void l0_out_kernel()
{
    int idx = blockIdx.x * 256 + threadIdx.x;     // < MROWS*1024
    int j = idx & 1023;
    int row = idx >> 10;
    const float* c = g_c6 + row * 8;
    float acc = g_b0eff[j];
#pragma unroll
    for (int i = 0; i < 6; i++) acc += c[i] * g_W0eff[i * 1024 + j];
    g_hr[(size_t)row * 1024 + j] = __float2half_rn(fmaxf(acc, 0.f));
}

// ---------------------------------------------------------------------------
// Materialize P' (fp16) + fused row-sum -> g_rz (L1/L2). One warp per row.
// ---------------------------------------------------------------------------
__global__ __launch_bounds__(256) void pgen_kernel()
{
    const int wid = threadIdx.x >> 5, lane = threadIdx.x & 31;
    const int t = blockIdx.x * 8 + wid;
    const int b = t >> 11;
    const float qa = g_qa[t], qb = g_qb[t];
    const uint32_t* wrow = g_adjT + (size_t)t * (NN / 32);
    const float* f1 = g_f1 + b * NN;
    const float* f2 = g_f2 + b * NN;
    __half* Prow = g_P + (size_t)t * NN;
    float sum = 0.f;
#pragma unroll 4
    for (int i = 0; i < 16; i++) {
        const int s = i * 128 + lane * 4;
        const uint32_t w = wrow[s >> 5];
        const uint32_t sh = s & 31;
        float4 x1 = *reinterpret_cast<const float4*>(f1 + s);
        float4 x2 = *reinterpret_cast<const float4*>(f2 + s);
        float o0 = ((w >> (sh + 0)) & 1u) ? fmaxf(qa * x1.x, qb * x2.x) : 0.f;
        float o1 = ((w >> (sh + 1)) & 1u) ? fmaxf(qa * x1.y, qb * x2.y) : 0.f;
        float o2 = ((w >> (sh + 2)) & 1u) ? fmaxf(qa * x1.z, qb * x2.z) : 0.f;
        float o3 = ((w >> (sh + 3)) & 1u) ? fmaxf(qa * x1.w, qb * x2.w) : 0.f;
        __half2 p01 = __floats2half2_rn(o0, o1);
        __half2 p23 = __floats2half2_rn(o2, o3);
        float2 q01 = __half22float2(p01);
        float2 q23 = __half22float2(p23);
        sum += (q01.x + q01.y) + (q23.x + q23.y);
        *reinterpret_cast<__half2*>(Prow + s)     = p01;
        *reinterpret_cast<__half2*>(Prow + s + 2) = p23;
    }
#pragma unroll
    for (int off = 16; off; off >>= 1) sum += __shfl_xor_sync(0xFFFFFFFFu, sum, off);
    if (lane == 0) g_rz[t] = 1.f / fmaxf(sum, 1e-30f);
}

// ---------------------------------------------------------------------------
// Host launcher
// ---------------------------------------------------------------------------
extern "C" void kernel_launch(void* const* d_in, const int* in_sizes, int n_in,
                              void* d_out, int out_size)
{
    const int*   adj      = (const int*)d_in[0];
    const float* arrivals = (const float*)d_in[1];
    const float* depart   = (const float*)d_in[2];
    const float* hard     = (const float*)d_in[3];
    const float* active   = (const float*)d_in[4];
    const float* timestep = (const float*)d_in[5];
    const float* totalts  = (const float*)d_in[6];
    const float* embW1 = (const float*)d_in[7];
    const float* embb1 = (const float*)d_in[8];
    const float* embW2 = (const float*)d_in[9];
    const float* embb2 = (const float*)d_in[10];
    const float* gatW[3]    = {(const float*)d_in[11], (const float*)d_in[15], (const float*)d_in[19]};
    const float* gatAsrc[3] = {(const float*)d_in[12], (const float*)d_in[16], (const float*)d_in[20]};
    const float* gatAdst[3] = {(const float*)d_in[13], (const float*)d_in[17], (const float*)d_in[21]};
    const float* gatB[3]    = {(const float*)d_in[14], (const float*)d_in[18], (const float*)d_in[22]};
    const float* ffW1 = (const float*)d_in[23];
    const float* ffb1 = (const float*)d_in[24];
    const float* ffW2 = (const float*)d_in[25];
    const float* ffb2 = (const float*)d_in[26];

    float *x, *h, *rz, *ee;
    __half *xr, *hr, *hwt, *P, *wt;
    cudaGetSymbolAddress((void**)&x,   g_x);
    cudaGetSymbolAddress((void**)&xr,  g_xr);
    cudaGetSymbolAddress((void**)&h,   g_h);
    cudaGetSymbolAddress((void**)&hr,  g_hr);
    cudaGetSymbolAddress((void**)&hwt, g_hwt);
    cudaGetSymbolAddress((void**)&P,   g_P);
    cudaGetSymbolAddress((void**)&rz,  g_rz);
    cudaGetSymbolAddress((void**)&wt,  g_wt);
    cudaGetSymbolAddress((void**)&ee,  g_ee);

    static int smem_set = 0;
    if (!smem_set) {
        cudaFuncSetAttribute(gemm_tc<0>, cudaFuncAttributeMaxDynamicSharedMemorySize, SMEM_BYTES);
        cudaFuncSetAttribute(gemm_tc<1>, cudaFuncAttributeMaxDynamicSharedMemorySize, SMEM_BYTES);
        cudaFuncSetAttribute(gemm_tc<2>, cudaFuncAttributeMaxDynamicSharedMemorySize, SMEM_BYTES);
        cudaFuncSetAttribute(gemm_tc<3>, cudaFuncAttributeMaxDynamicSharedMemorySize, SMEM_BYTES);
        cudaFuncSetAttribute(gemm_tc<4>, cudaFuncAttributeMaxDynamicSharedMemorySize, SMEM_BYTES);
        cudaFuncSetAttribute(pgen_l0_kernel, cudaFuncAttributeMaxDynamicSharedMemorySize, 65536);
        smem_set = 1;
    }

    // Prep + embedding + adjacency
    prep_weff_kernel<<<2, 256>>>(embW1, embb1, embW2, embb2);
    prep_l0a_kernel<<<4, 256>>>(gatW[0], gatB[0]);
    prep_l0b_kernel<<<1, 256>>>(gatAsrc[0], gatAdst[0]);
    embed_kernel<<<(MROWS * HH) / 256, 256>>>(arrivals, depart, hard, timestep, totalts);
    feats_kernel<<<MROWS / 256, 256>>>(arrivals, depart, hard, timestep, totalts);
    adjT_kernel<<<dim3(NN / 32, NN / 32, NB), 1024>>>(adj);

    // ---- Layer 0: rank-6 collapsed attention ----
    zero_ee2_kernel<<<(2 * MROWS) / 256, 256>>>();   // resets smax (ee overwritten below)
    l0_e_kernel<<<MROWS / 256, 256>>>();
    smax_kernel<<<MROWS / 256, 256>>>();
    nodeprep_kernel<<<MROWS / 256, 256>>>();
    pgen_l0_kernel<<<MROWS / 8, 256, 65536>>>();
    l0_out_kernel<<<(MROWS * 1024) / 256, 256>>>();

    // ---- Layers 1, 2: dense path ----
    const int Kin[3] = {0, 1024, 1024};
    const int Fo[3]  = {0, 1024, HH};
    const dim3 tblk(32, 8);
    for (int l = 1; l < 3; l++) {
        transpose_kernel<<<dim3(Fo[l] / 32, Kin[l] / 32), tblk>>>(gatW[l], wt, Kin[l], Fo[l]);
        zero_ee2_kernel<<<(2 * MROWS) / 256, 256>>>();
        gemm_tc<0><<<dim3(Fo[l] / 128, MROWS / 128), 256, SMEM_BYTES>>>(
            hr, wt, nullptr, hwt, Kin[l], Fo[l], gatAsrc[l], gatAdst[l], nullptr, nullptr, ee);
        smax_kernel<<<MROWS / 256, 256>>>();
        nodeprep_kernel<<<MROWS / 256, 256>>>();
        pgen_kernel<<<MROWS / 8, 256>>>();
        if (l < 2) {
            gemm_tc<1><<<dim3(Fo[l] / 128, NN / 128, NB), 256, SMEM_BYTES>>>(
                P, hwt, nullptr, hr, NN, Fo[l], gatB[l], nullptr, nullptr, rz, nullptr);
        } else {
            gemm_tc<2><<<dim3(Fo[l] / 128, NN / 128, NB), 256, SMEM_BYTES>>>(
                P, hwt, h, hr, NN, Fo[l], gatB[l], x, nullptr, rz, nullptr);
        }
    }

    // ff1: x2 = x1 + relu(x1 @ W1 + b1)
    transpose_kernel<<<dim3(HH / 32, HH / 32), tblk>>>(ffW1, wt, HH, HH);
    gemm_tc<3><<<dim3(HH / 128, MROWS / 128), 256, SMEM_BYTES>>>(
        hr, wt, x, xr, HH, HH, ffb1, h, nullptr, nullptr, nullptr);
    // ff2: out = (x2 + relu(x2 @ W2 + b2)) * active
    transpose_kernel<<<dim3(HH / 32, HH / 32), tblk>>>(ffW2, wt, HH, HH);
    gemm_tc<4><<<dim3(HH / 128, MROWS / 128), 256, SMEM_BYTES>>>(
        xr, wt, (float*)d_out, nullptr, HH, HH, ffb2, x, active, nullptr, nullptr);
}

// round 13
// speedup vs baseline: 1.1755x; 1.1755x over previous
#include <cuda_runtime.h>
#include <cuda_fp16.h>
#include <cstdint>

#define NB 8
#define NN 2048
#define HH 512
#define MROWS (NB * NN)   // 16384

// ---------------------------------------------------------------------------
// Scratch (device globals — no allocation allowed)
// ---------------------------------------------------------------------------
__device__ float  g_x[MROWS * HH];                 // residual x (fp32)
__device__ __half g_xr[MROWS * HH];                // fp16 copy of x
__device__ float  g_h[MROWS * 1024];               // fp32 activations (layer-2 only)
__device__ __half g_hr[MROWS * 1024];              // fp16 activations
__device__ __half g_hwt[(size_t)1024 * MROWS];     // (h @ W)^T [Fo][MROWS], fp16
__device__ __half g_P[(size_t)MROWS * NN];         // unnormalized attention, fp16 (L1/L2)
__device__ __half g_wt[1024 * 1024];               // W^T [N][K], fp16
__device__ uint32_t g_adjT[MROWS * (NN / 32)];     // bit: valid(t, s), self-loop folded
__device__ float  g_ee[2 * MROWS];                 // [0..M) esrc, [M..2M) edst
__device__ float  g_f1[MROWS], g_f2[MROWS];        // per-source exp factors
__device__ float  g_qa[MROWS], g_qb[MROWS];        // per-target exp factors
__device__ float  g_rz[MROWS];                     // 1 / row-sum of P'
__device__ unsigned int g_smax_bits[NB];           // orderable-int max of esrc per batch
__device__ float  g_Weff[6 * HH];
__device__ float  g_beff[HH];
// Layer-0 rank-6 path (feature-major: g_feats[(b*8+q)*NN + s])
__device__ float  g_feats[NB * 8 * NN];
__device__ float  g_c6[MROWS * 8];                 // P-hat @ feats (rz-scaled), padded
__device__ float  g_W0eff[6 * 1024];               // Weff @ W0
__device__ float  g_b0w[1024];                     // beff @ W0
__device__ float  g_b0eff[1024];                   // beff @ W0 + gat_b0
__device__ float  g_v6[14];                        // [0..6) vsrc6, [6..12) vdst6, [12] c_src, [13] c_dst

// ---------------------------------------------------------------------------
// Helpers
// ---------------------------------------------------------------------------
__device__ __forceinline__ unsigned enc_ord(float f) {
    unsigned i = __float_as_uint(f);
    return (i & 0x80000000u) ? ~i : (i | 0x80000000u);
}
__device__ __forceinline__ float dec_ord(unsigned k) {
    unsigned i = (k & 0x80000000u) ? (k & 0x7FFFFFFFu) : ~k;
    return __uint_as_float(i);
}
__device__ __forceinline__ uint32_t smem_u32(const void* p) {
    uint32_t a;
    asm("{ .reg .u64 t; cvta.to.shared.u64 t, %1; cvt.u32.u64 %0, t; }" : "=r"(a) : "l"(p));
    return a;
}
__device__ __forceinline__ void mma16(float* c, const uint32_t* a, const uint32_t* b) {
    asm volatile(
        "mma.sync.aligned.m16n8k16.row.col.f32.f16.f16.f32 "
        "{%0,%1,%2,%3}, {%4,%5,%6,%7}, {%8,%9}, {%0,%1,%2,%3};"
        : "+f"(c[0]), "+f"(c[1]), "+f"(c[2]), "+f"(c[3])
        : "r"(a[0]), "r"(a[1]), "r"(a[2]), "r"(a[3]), "r"(b[0]), "r"(b[1]));
}
__device__ __forceinline__ void ldsm4(uint32_t* r, uint32_t addr) {
    asm volatile("ldmatrix.sync.aligned.m8n8.x4.shared.b16 {%0,%1,%2,%3}, [%4];"
                 : "=r"(r[0]), "=r"(r[1]), "=r"(r[2]), "=r"(r[3]) : "r"(addr));
}
#define CPA(dst, src) asm volatile("cp.async.cg.shared.global [%0], [%1], 16;" :: "r"(dst), "l"(src))
#define CPC() asm volatile("cp.async.commit_group;")
#define CPW(n) asm volatile("cp.async.wait_group %0;" :: "n"(n))

// k-major fp16 tile: 128 rows x 64 halfs (128 bytes/row). 16B chunk c4k = 0..7.
#define SOFFB(row, c4k) ((row) * 128 + ((((c4k)) ^ ((row) & 7)) << 4))

#define STAGE_BYTES 32768                 // A 16KB + B 16KB per stage (kt = 64)
#define SMEM_BYTES (3 * STAGE_BYTES)      // 96 KB, 2 CTAs/SM

// ---------------------------------------------------------------------------
// Unified fp16 tensor-core GEMM (fp32 accumulate).
// EPI 0: Ch^T[n][m] = h(acc); fused esrc/edst dots
// EPI 1: Ch = h(relu(acc*rz + bias))               (attention mid, batched)
// EPI 2: C = acc*rz + bias + X; Ch = h(C)          (attention last, batched)
// EPI 3: C = X + relu(acc + bias); Ch = h(C)       (ff1)
// EPI 4: C = (X + relu(acc + bias)) * act[row]     (ff2)
// ---------------------------------------------------------------------------
template <int EPI>
__global__ __launch_bounds__(256, 2) void gemm_tc(
    const __half* __restrict__ A, const __half* __restrict__ Bt,
    float* __restrict__ C, __half* __restrict__ Ch, int K, int N,
    const float* __restrict__ bias, const float* __restrict__ X,
    const float* __restrict__ act, const float* __restrict__ rz,
    float* __restrict__ ee)
{
    constexpr bool BATCHED = (EPI == 1 || EPI == 2);
    extern __shared__ char smc[];
    const uint32_t sbase = smem_u32(smc);
    const int tid = threadIdx.x;
    const int lane = tid & 31, wid = tid >> 5;

    int bx = blockIdx.x, by = blockIdx.y;
    {
        const int GX = gridDim.x;
        const int lin = by * GX + bx;
        const int grp = lin / (4 * GX);
        const int rem = lin - grp * 4 * GX;
        by = grp * 4 + (rem & 3);
        bx = rem >> 2;
    }
    const int m0 = by * 128, n0 = bx * 128;
    const int ws = wid >> 2, wcs = wid & 3;
    const int wm = ws * 64, wn = wcs * 32;

    int zoff = 0;
    if (BATCHED) zoff = blockIdx.z * NN;
    const __half* Ab = A + (size_t)zoff * K;
    const int ldb = BATCHED ? MROWS : K;
    const int kboff = BATCHED ? zoff : 0;
    float* Cb = (C != nullptr) ? C + (size_t)zoff * N : nullptr;
    __half* Chb = (Ch != nullptr && EPI != 0) ? Ch + (size_t)zoff * N : Ch;
    const float* Xb = (EPI >= 2) ? X + (size_t)zoff * N : nullptr;
    const float* rzb = BATCHED ? rz + zoff : nullptr;

    float acc[4][4][4];
#pragma unroll
    for (int i = 0; i < 4; i++)
#pragma unroll
        for (int j = 0; j < 4; j++)
#pragma unroll
            for (int q = 0; q < 4; q++) acc[i][j][q] = 0.f;

    const int row_l = tid >> 3, c4_l = tid & 7;

    auto issue = [&](int kt) {
        const int k0 = kt << 6;
        const uint32_t aB = sbase + (kt % 3) * STAGE_BYTES;
        const uint32_t bB = aB + 16384;
#pragma unroll
        for (int p = 0; p < 4; p++) {
            const int row = row_l + p * 32;
            const uint32_t so = SOFFB(row, c4_l);
            CPA(aB + so, Ab + (size_t)(m0 + row) * K + k0 + c4_l * 8);
            CPA(bB + so, Bt + (size_t)(n0 + row) * ldb + kboff + k0 + c4_l * 8);
        }
        CPC();
    };

    const int mA_row = lane & 15, mA_k = lane >> 4;
    const int nB_row = (lane & 7) + ((lane >> 4) << 3);
    const int nB_k = (lane >> 3) & 1;

    auto compute = [&](int stg) {
        const uint32_t aB = sbase + stg * STAGE_BYTES;
        const uint32_t bB = aB + 16384;
#pragma unroll
        for (int kk = 0; kk < 4; kk++) {
            uint32_t fa[4][4], fb[2][4];
#pragma unroll
            for (int mf = 0; mf < 4; mf++)
                ldsm4(fa[mf], aB + SOFFB(wm + mf * 16 + mA_row, kk * 2 + mA_k));
#pragma unroll
            for (int bp = 0; bp < 2; bp++)
                ldsm4(fb[bp], bB + SOFFB(wn + bp * 16 + nB_row, kk * 2 + nB_k));
#pragma unroll
            for (int mf = 0; mf < 4; mf++)
#pragma unroll
                for (int nf = 0; nf < 4; nf++)
                    mma16(acc[mf][nf], fa[mf], &fb[nf >> 1][(nf & 1) * 2]);
        }
    };

    const int nkt = K >> 6;
    issue(0);
    issue(1);
    for (int kt = 0; kt < nkt; kt++) {
        if (kt < nkt - 1) { CPW(1); } else { CPW(0); }
        __syncthreads();
        if (kt + 2 < nkt) issue(kt + 2);
        compute(kt % 3);
    }

#pragma unroll
    for (int mf = 0; mf < 4; mf++) {
#pragma unroll
        for (int rr = 0; rr < 2; rr++) {
            const int r = m0 + wm + mf * 16 + (lane >> 2) + rr * 8;
            float rzv = 1.f, actv = 1.f;
            if (BATCHED) rzv = rzb[r];
            if (EPI == 4) actv = act[r];
            float sE = 0.f, sD = 0.f;
#pragma unroll
            for (int nf = 0; nf < 4; nf++) {
                const int cc = n0 + wn + nf * 8 + (lane & 3) * 2;
                float v0 = acc[mf][nf][rr * 2 + 0];
                float v1 = acc[mf][nf][rr * 2 + 1];
                if (EPI == 0) {
                    const __half h0 = __float2half_rn(v0);
                    const __half h1 = __float2half_rn(v1);
                    Ch[(size_t)cc * MROWS + r]       = h0;
                    Ch[(size_t)(cc + 1) * MROWS + r] = h1;
                    const float c0 = __half2float(h0), c1 = __half2float(h1);
                    sE += c0 * bias[cc] + c1 * bias[cc + 1];
                    sD += c0 * X[cc] + c1 * X[cc + 1];
                } else {
                    if (BATCHED) { v0 *= rzv; v1 *= rzv; }
                    v0 += bias[cc]; v1 += bias[cc + 1];
                    if (EPI == 1) {
                        v0 = fmaxf(v0, 0.f); v1 = fmaxf(v1, 0.f);
                        *reinterpret_cast<__half2*>(Chb + (size_t)r * N + cc) =
                            __floats2half2_rn(v0, v1);
                    } else {
                        if (EPI == 2) {
                            const float* xr = Xb + (size_t)r * N + cc;
                            v0 += xr[0]; v1 += xr[1];
                        } else if (EPI == 3) {
                            const float* xr = Xb + (size_t)r * N + cc;
                            v0 = xr[0] + fmaxf(v0, 0.f); v1 = xr[1] + fmaxf(v1, 0.f);
                        } else if (EPI == 4) {
                            const float* xr = Xb + (size_t)r * N + cc;
                            v0 = (xr[0] + fmaxf(v0, 0.f)) * actv;
                            v1 = (xr[1] + fmaxf(v1, 0.f)) * actv;
                        }
                        *reinterpret_cast<float2*>(Cb + (size_t)r * N + cc) = make_float2(v0, v1);
                        if (EPI == 2 || EPI == 3) {
                            *reinterpret_cast<__half2*>(Chb + (size_t)r * N + cc) =
                                __floats2half2_rn(v0, v1);
                        }
                    }
                }
            }
            if (EPI == 0) {
                sE += __shfl_xor_sync(0xFFFFFFFFu, sE, 1);
                sE += __shfl_xor_sync(0xFFFFFFFFu, sE, 2);
                sD += __shfl_xor_sync(0xFFFFFFFFu, sD, 1);
                sD += __shfl_xor_sync(0xFFFFFFFFu, sD, 2);
                if ((lane & 3) == 0) {
                    atomicAdd(ee + r, sE);
                    atomicAdd(ee + MROWS + r, sD);
                }
            }
        }
    }
}

// ---------------------------------------------------------------------------
// 32x32 tiled transpose to fp16
// ---------------------------------------------------------------------------
__global__ void transpose_kernel(const float* __restrict__ in, __half* __restrict__ out,
                                 int R, int Cc)
{
    __shared__ float tile[32][33];
    int c0 = blockIdx.x * 32, r0 = blockIdx.y * 32;
    int x = threadIdx.x, y = threadIdx.y;
#pragma unroll
    for (int i = 0; i < 32; i += 8)
        tile[y + i][x] = in[(size_t)(r0 + y + i) * Cc + c0 + x];
    __syncthreads();
#pragma unroll
    for (int i = 0; i < 32; i += 8)
        out[(size_t)(c0 + y + i) * R + r0 + x] = __float2half_rn(tile[x][y + i]);
}

// ---------------------------------------------------------------------------
// adjT: bit s of word (b,t,s/32) = (adj[b][s][t]!=0) | (s==t)
// ---------------------------------------------------------------------------
__global__ __launch_bounds__(1024) void adjT_kernel(const int* __restrict__ adj)
{
    __shared__ int sa[32][33];
    const int b = blockIdx.z, t0 = blockIdx.y * 32, s0 = blockIdx.x * 32;
    const int w = threadIdx.x >> 5, lane = threadIdx.x & 31;
    sa[w][lane] = adj[((size_t)b * NN + s0 + w) * NN + t0 + lane];
    __syncthreads();
    const int t = t0 + w;
    uint32_t word = __ballot_sync(0xFFFFFFFFu, sa[lane][w] != 0);
    if (lane == 0) {
        if ((t >> 5) == (s0 >> 5)) word |= 1u << (t & 31);
        g_adjT[((size_t)b * NN + t) * (NN / 32) + (s0 >> 5)] = word;
    }
}

// ---------------------------------------------------------------------------
// Weff = emb_W1 @ emb_W2 ; beff = emb_b1 @ emb_W2 + emb_b2
// ---------------------------------------------------------------------------
__global__ void prep_weff_kernel(const float* __restrict__ W1, const float* __restrict__ b1,
                                 const float* __restrict__ W2, const float* __restrict__ b2)
{
    int j = blockIdx.x * 256 + threadIdx.x;
    if (j >= HH) return;
    float acc[6] = {0.f, 0.f, 0.f, 0.f, 0.f, 0.f};
    float bacc = b2[j];
    for (int k = 0; k < HH; k++) {
        float w2 = W2[k * HH + j];
        bacc += b1[k] * w2;
#pragma unroll
        for (int i = 0; i < 6; i++) acc[i] += W1[i * HH + k] * w2;
    }
#pragma unroll
    for (int i = 0; i < 6; i++) g_Weff[i * HH + j] = acc[i];
    g_beff[j] = bacc;
}

// ---------------------------------------------------------------------------
// W0eff = Weff @ W0 [6x1024]; b0w = beff @ W0; b0eff = b0w + gat_b0
// ---------------------------------------------------------------------------
__global__ void prep_l0a_kernel(const float* __restrict__ W0, const float* __restrict__ b0)
{
    int j = blockIdx.x * 256 + threadIdx.x;
    if (j >= 1024) return;
    float acc[6] = {0.f, 0.f, 0.f, 0.f, 0.f, 0.f};
    float bw = 0.f;
    for (int k = 0; k < HH; k++) {
        float w0 = W0[(size_t)k * 1024 + j];
        bw += g_beff[k] * w0;
#pragma unroll
        for (int i = 0; i < 6; i++) acc[i] += g_Weff[i * HH + k] * w0;
    }
#pragma unroll
    for (int i = 0; i < 6; i++) g_W0eff[i * 1024 + j] = acc[i];
    g_b0w[j] = bw;
    g_b0eff[j] = bw + b0[j];
}

// ---------------------------------------------------------------------------
// vsrc6[i] = W0eff[i]·a_src; vdst6[i] = W0eff[i]·a_dst; c_src = b0w·a_src; c_dst
// ---------------------------------------------------------------------------
__global__ __launch_bounds__(256) void prep_l0b_kernel(const float* __restrict__ asrc,
                                                       const float* __restrict__ adst)
{
    __shared__ float red[14][256];
    const int t = threadIdx.x;
    float p[14];
#pragma unroll
    for (int q = 0; q < 14; q++) p[q] = 0.f;
    for (int j = t; j < 1024; j += 256) {
        float as = asrc[j], ad = adst[j], bw = g_b0w[j];
#pragma unroll
        for (int i = 0; i < 6; i++) {
            float w = g_W0eff[i * 1024 + j];
            p[i] += w * as;
            p[6 + i] += w * ad;
        }
        p[12] += bw * as;
        p[13] += bw * ad;
    }
#pragma unroll
    for (int q = 0; q < 14; q++) red[q][t] = p[q];
    __syncthreads();
    for (int s = 128; s; s >>= 1) {
        if (t < s) {
#pragma unroll
            for (int q = 0; q < 14; q++) red[q][t] += red[q][t + s];
        }
        __syncthreads();
    }
    if (t < 14) g_v6[t] = red[t][0];
}

// ---------------------------------------------------------------------------
// Features, feature-major per batch: g_feats[(b*8+q)*NN + s]
// ---------------------------------------------------------------------------
__global__ void feats_kernel(const float* __restrict__ arr, const float* __restrict__ dep,
                             const float* __restrict__ hard,
                             const float* __restrict__ ts, const float* __restrict__ tt)
{
    int row = blockIdx.x * 256 + threadIdx.x;
    int b = row >> 11;
    int s = row & (NN - 1);
    float t = ts[b], T = tt[b];
    float ar = arr[row], de = dep[row];
    float f[6];
    f[0] = (t - ar) / (de - ar);
    f[1] = t / T;
    f[2] = fmodf(f[1], 2.f);
    f[3] = fmodf(f[1], 4.f);
    f[4] = fmodf(f[1], 7.f);
    f[5] = hard[row];
    float* base = g_feats + (size_t)b * 8 * NN + s;
#pragma unroll
    for (int q = 0; q < 6; q++) base[q * NN] = f[q];
}

// ---------------------------------------------------------------------------
// Feature construction + fused 6->512 embedding; writes x (fp32) and xr (fp16)
// ---------------------------------------------------------------------------
__global__ void embed_kernel(const float* __restrict__ arr, const float* __restrict__ dep,
                             const float* __restrict__ hard,
                             const float* __restrict__ ts, const float* __restrict__ tt)
{
    int idx = blockIdx.x * 256 + threadIdx.x;
    int j = idx & (HH - 1);
    int row = idx >> 9;
    int b = row >> 11;
    float t = ts[b], T = tt[b];
    float ar = arr[row], de = dep[row];
    float f[6];
    f[0] = (t - ar) / (de - ar);
    f[1] = t / T;
    f[2] = fmodf(f[1], 2.f);
    f[3] = fmodf(f[1], 4.f);
    f[4] = fmodf(f[1], 7.f);
    f[5] = hard[row];
    float acc = g_beff[j];
#pragma unroll
    for (int i = 0; i < 6; i++) acc += f[i] * g_Weff[i * HH + j];
    g_x[idx] = acc;
    g_xr[idx] = __float2half_rn(acc);
}

// ---------------------------------------------------------------------------
// Layer-0 e_src/e_dst via rank-6: e = feats·v6 + const
// ---------------------------------------------------------------------------
__global__ void l0_e_kernel()
{
    int row = blockIdx.x * 256 + threadIdx.x;
    int b = row >> 11;
    int s = row & (NN - 1);
    const float* base = g_feats + (size_t)b * 8 * NN + s;
    float es = g_v6[12], ed = g_v6[13];
#pragma unroll
    for (int i = 0; i < 6; i++) {
        float fv = base[i * NN];
        es += fv * g_v6[i];
        ed += fv * g_v6[6 + i];
    }
    g_ee[row] = es;
    g_ee[MROWS + row] = ed;
}

// ---------------------------------------------------------------------------
// Reset per-batch smax + zero ee
// ---------------------------------------------------------------------------
__global__ void zero_ee2_kernel()
{
    int i = blockIdx.x * 256 + threadIdx.x;
    if (i < 2 * MROWS) g_ee[i] = 0.f;
    if (i < NB) g_smax_bits[i] = 0x007FFFFFu;  // enc(-inf)
}

// ---------------------------------------------------------------------------
// Per-batch max of esrc -> g_smax_bits
// ---------------------------------------------------------------------------
__global__ __launch_bounds__(256) void smax_kernel()
{
    const int i = blockIdx.x * 256 + threadIdx.x;
    float v = g_ee[i];
#pragma unroll
    for (int off = 16; off; off >>= 1)
        v = fmaxf(v, __shfl_xor_sync(0xFFFFFFFFu, v, off));
    __shared__ float red[8];
    const int w = threadIdx.x >> 5, l = threadIdx.x & 31;
    if (l == 0) red[w] = v;
    __syncthreads();
    if (threadIdx.x == 0) {
        float m = red[0];
#pragma unroll
        for (int q = 1; q < 8; q++) m = fmaxf(m, red[q]);
        atomicMax(&g_smax_bits[i >> 11], enc_ord(m));
    }
}

// ---------------------------------------------------------------------------
// Per-node exp factors (all exponents <= 0 -> no overflow)
// ---------------------------------------------------------------------------
__global__ void nodeprep_kernel()
{
    int t = blockIdx.x * 256 + threadIdx.x;
    int b = t >> 11;
    float sm = dec_ord(g_smax_bits[b]);
    float es = g_ee[t], ed = g_ee[MROWS + t];
    g_f1[t] = __expf(es - sm);
    g_f2[t] = __expf(0.2f * (es - sm));
    float u = ed + sm;
    float mh = fmaxf(u, 0.2f * u);
    g_qa[t] = __expf(u - mh);
    g_qb[t] = __expf(0.2f * u - mh);
}

// ---------------------------------------------------------------------------
// L0 fused pgen: generate P row in registers, accumulate Z and P@feats.
// Feature-major smem [6][2048] -> conflict-free float4 loads.
// ---------------------------------------------------------------------------
__global__ __launch_bounds__(256) void pgen_l0_kernel()
{
    extern __shared__ float sf[];   // [6][2048] feats for this block's batch
    const int tid = threadIdx.x;
    const int wid = tid >> 5, lane = tid & 31;
    const int t = blockIdx.x * 8 + wid;
    const int b = t >> 11;
    {
        const float4* src = reinterpret_cast<const float4*>(g_feats + (size_t)b * 8 * NN);
        float4* dst = reinterpret_cast<float4*>(sf);
        for (int i = tid; i < 6 * NN / 4; i += 256) dst[i] = src[i];
    }
    __syncthreads();

    const float qa = g_qa[t], qb = g_qb[t];
    const uint32_t* wrow = g_adjT + (size_t)t * (NN / 32);
    const float* f1 = g_f1 + b * NN;
    const float* f2 = g_f2 + b * NN;
    float sum = 0.f;
    float c[6] = {0.f, 0.f, 0.f, 0.f, 0.f, 0.f};
#pragma unroll 2
    for (int i = 0; i < 16; i++) {
        const int s = i * 128 + lane * 4;
        const uint32_t w = wrow[s >> 5];
        const uint32_t sh = s & 31;
        float4 x1 = *reinterpret_cast<const float4*>(f1 + s);
        float4 x2 = *reinterpret_cast<const float4*>(f2 + s);
        float o0 = ((w >> (sh + 0)) & 1u) ? fmaxf(qa * x1.x, qb * x2.x) : 0.f;
        float o1 = ((w >> (sh + 1)) & 1u) ? fmaxf(qa * x1.y, qb * x2.y) : 0.f;
        float o2 = ((w >> (sh + 2)) & 1u) ? fmaxf(qa * x1.z, qb * x2.z) : 0.f;
        float o3 = ((w >> (sh + 3)) & 1u) ? fmaxf(qa * x1.w, qb * x2.w) : 0.f;
        sum += (o0 + o1) + (o2 + o3);
#pragma unroll
        for (int q = 0; q < 6; q++) {
            const float4 fq = *reinterpret_cast<const float4*>(sf + q * NN + s);
            c[q] += o0 * fq.x + o1 * fq.y + o2 * fq.z + o3 * fq.w;
        }
    }
#pragma unroll
    for (int off = 16; off; off >>= 1) {
        sum += __shfl_xor_sync(0xFFFFFFFFu, sum, off);
#pragma unroll
        for (int q = 0; q < 6; q++) c[q] += __shfl_xor_sync(0xFFFFFFFFu, c[q], off);
    }
    if (lane == 0) {
        const float rzv = 1.f / fmaxf(sum, 1e-30f);
        g_rz[t] = rzv;
        float* co = g_c6 + t * 8;
#pragma unroll
        for (int q = 0; q < 6; q++) co[q] = c[q] * rzv;
    }
}

// ---------------------------------------------------------------------------
// L0 output: hr[t][j] = h(relu( c6[t]·W0eff[:,j] + b0eff[j] ))
// ---------------------------------------------------------------------------
__global__ void l0_out_kernel()
{
    int idx = blockIdx.x * 256 + threadIdx.x;     // < MROWS*1024
    int j = idx & 1023;
    int row = idx >> 10;
    const float* c = g_c6 + row * 8;
    float acc = g_b0eff[j];
#pragma unroll
    for (int i = 0; i < 6; i++) acc += c[i] * g_W0eff[i * 1024 + j];
    g_hr[(size_t)row * 1024 + j] = __float2half_rn(fmaxf(acc, 0.f));
}

// ---------------------------------------------------------------------------
// Materialize P' (fp16) + fused row-sum -> g_rz (L1/L2). One warp per row.
// ---------------------------------------------------------------------------
__global__ __launch_bounds__(256) void pgen_kernel()
{
    const int wid = threadIdx.x >> 5, lane = threadIdx.x & 31;
    const int t = blockIdx.x * 8 + wid;
    const int b = t >> 11;
    const float qa = g_qa[t], qb = g_qb[t];
    const uint32_t* wrow = g_adjT + (size_t)t * (NN / 32);
    const float* f1 = g_f1 + b * NN;
    const float* f2 = g_f2 + b * NN;
    __half* Prow = g_P + (size_t)t * NN;
    float sum = 0.f;
#pragma unroll 4
    for (int i = 0; i < 16; i++) {
        const int s = i * 128 + lane * 4;
        const uint32_t w = wrow[s >> 5];
        const uint32_t sh = s & 31;
        float4 x1 = *reinterpret_cast<const float4*>(f1 + s);
        float4 x2 = *reinterpret_cast<const float4*>(f2 + s);
        float o0 = ((w >> (sh + 0)) & 1u) ? fmaxf(qa * x1.x, qb * x2.x) : 0.f;
        float o1 = ((w >> (sh + 1)) & 1u) ? fmaxf(qa * x1.y, qb * x2.y) : 0.f;
        float o2 = ((w >> (sh + 2)) & 1u) ? fmaxf(qa * x1.z, qb * x2.z) : 0.f;
        float o3 = ((w >> (sh + 3)) & 1u) ? fmaxf(qa * x1.w, qb * x2.w) : 0.f;
        __half2 p01 = __floats2half2_rn(o0, o1);
        __half2 p23 = __floats2half2_rn(o2, o3);
        float2 q01 = __half22float2(p01);
        float2 q23 = __half22float2(p23);
        sum += (q01.x + q01.y) + (q23.x + q23.y);
        *reinterpret_cast<__half2*>(Prow + s)     = p01;
        *reinterpret_cast<__half2*>(Prow + s + 2) = p23;
    }
#pragma unroll
    for (int off = 16; off; off >>= 1) sum += __shfl_xor_sync(0xFFFFFFFFu, sum, off);
    if (lane == 0) g_rz[t] = 1.f / fmaxf(sum, 1e-30f);
}

// ---------------------------------------------------------------------------
// Host launcher
// ---------------------------------------------------------------------------
extern "C" void kernel_launch(void* const* d_in, const int* in_sizes, int n_in,
                              void* d_out, int out_size)
{
    const int*   adj      = (const int*)d_in[0];
    const float* arrivals = (const float*)d_in[1];
    const float* depart   = (const float*)d_in[2];
    const float* hard     = (const float*)d_in[3];
    const float* active   = (const float*)d_in[4];
    const float* timestep = (const float*)d_in[5];
    const float* totalts  = (const float*)d_in[6];
    const float* embW1 = (const float*)d_in[7];
    const float* embb1 = (const float*)d_in[8];
    const float* embW2 = (const float*)d_in[9];
    const float* embb2 = (const float*)d_in[10];
    const float* gatW[3]    = {(const float*)d_in[11], (const float*)d_in[15], (const float*)d_in[19]};
    const float* gatAsrc[3] = {(const float*)d_in[12], (const float*)d_in[16], (const float*)d_in[20]};
    const float* gatAdst[3] = {(const float*)d_in[13], (const float*)d_in[17], (const float*)d_in[21]};
    const float* gatB[3]    = {(const float*)d_in[14], (const float*)d_in[18], (const float*)d_in[22]};
    const float* ffW1 = (const float*)d_in[23];
    const float* ffb1 = (const float*)d_in[24];
    const float* ffW2 = (const float*)d_in[25];
    const float* ffb2 = (const float*)d_in[26];

    float *x, *h, *rz, *ee;
    __half *xr, *hr, *hwt, *P, *wt;
    cudaGetSymbolAddress((void**)&x,   g_x);
    cudaGetSymbolAddress((void**)&xr,  g_xr);
    cudaGetSymbolAddress((void**)&h,   g_h);
    cudaGetSymbolAddress((void**)&hr,  g_hr);
    cudaGetSymbolAddress((void**)&hwt, g_hwt);
    cudaGetSymbolAddress((void**)&P,   g_P);
    cudaGetSymbolAddress((void**)&rz,  g_rz);
    cudaGetSymbolAddress((void**)&wt,  g_wt);
    cudaGetSymbolAddress((void**)&ee,  g_ee);

    static int smem_set = 0;
    if (!smem_set) {
        cudaFuncSetAttribute(gemm_tc<0>, cudaFuncAttributeMaxDynamicSharedMemorySize, SMEM_BYTES);
        cudaFuncSetAttribute(gemm_tc<1>, cudaFuncAttributeMaxDynamicSharedMemorySize, SMEM_BYTES);
        cudaFuncSetAttribute(gemm_tc<2>, cudaFuncAttributeMaxDynamicSharedMemorySize, SMEM_BYTES);
        cudaFuncSetAttribute(gemm_tc<3>, cudaFuncAttributeMaxDynamicSharedMemorySize, SMEM_BYTES);
        cudaFuncSetAttribute(gemm_tc<4>, cudaFuncAttributeMaxDynamicSharedMemorySize, SMEM_BYTES);
        cudaFuncSetAttribute(pgen_l0_kernel, cudaFuncAttributeMaxDynamicSharedMemorySize, 6 * NN * 4);
        smem_set = 1;
    }

    // Prep + embedding + adjacency
    prep_weff_kernel<<<2, 256>>>(embW1, embb1, embW2, embb2);
    prep_l0a_kernel<<<4, 256>>>(gatW[0], gatB[0]);
    prep_l0b_kernel<<<1, 256>>>(gatAsrc[0], gatAdst[0]);
    embed_kernel<<<(MROWS * HH) / 256, 256>>>(arrivals, depart, hard, timestep, totalts);
    feats_kernel<<<MROWS / 256, 256>>>(arrivals, depart, hard, timestep, totalts);
    adjT_kernel<<<dim3(NN / 32, NN / 32, NB), 1024>>>(adj);

    // ---- Layer 0: rank-6 collapsed attention ----
    zero_ee2_kernel<<<(2 * MROWS) / 256, 256>>>();   // resets smax (ee overwritten below)
    l0_e_kernel<<<MROWS / 256, 256>>>();
    smax_kernel<<<MROWS / 256, 256>>>();
    nodeprep_kernel<<<MROWS / 256, 256>>>();
    pgen_l0_kernel<<<MROWS / 8, 256, 6 * NN * 4>>>();
    l0_out_kernel<<<(MROWS * 1024) / 256, 256>>>();

    // ---- Layers 1, 2: dense path ----
    const int Kin[3] = {0, 1024, 1024};
    const int Fo[3]  = {0, 1024, HH};
    const dim3 tblk(32, 8);
    for (int l = 1; l < 3; l++) {
        transpose_kernel<<<dim3(Fo[l] / 32, Kin[l] / 32), tblk>>>(gatW[l], wt, Kin[l], Fo[l]);
        zero_ee2_kernel<<<(2 * MROWS) / 256, 256>>>();
        gemm_tc<0><<<dim3(Fo[l] / 128, MROWS / 128), 256, SMEM_BYTES>>>(
            hr, wt, nullptr, hwt, Kin[l], Fo[l], gatAsrc[l], gatAdst[l], nullptr, nullptr, ee);
        smax_kernel<<<MROWS / 256, 256>>>();
        nodeprep_kernel<<<MROWS / 256, 256>>>();
        pgen_kernel<<<MROWS / 8, 256>>>();
        if (l < 2) {
            gemm_tc<1><<<dim3(Fo[l] / 128, NN / 128, NB), 256, SMEM_BYTES>>>(
                P, hwt, nullptr, hr, NN, Fo[l], gatB[l], nullptr, nullptr, rz, nullptr);
        } else {
            gemm_tc<2><<<dim3(Fo[l] / 128, NN / 128, NB), 256, SMEM_BYTES>>>(
                P, hwt, h, hr, NN, Fo[l], gatB[l], x, nullptr, rz, nullptr);
        }
    }

    // ff1: x2 = x1 + relu(x1 @ W1 + b1)
    transpose_kernel<<<dim3(HH / 32, HH / 32), tblk>>>(ffW1, wt, HH, HH);
    gemm_tc<3><<<dim3(HH / 128, MROWS / 128), 256, SMEM_BYTES>>>(
        hr, wt, x, xr, HH, HH, ffb1, h, nullptr, nullptr, nullptr);
    // ff2: out = (x2 + relu(x2 @ W2 + b2)) * active
    transpose_kernel<<<dim3(HH / 32, HH / 32), tblk>>>(ffW2, wt, HH, HH);
    gemm_tc<4><<<dim3(HH / 128, MROWS / 128), 256, SMEM_BYTES>>>(
        xr, wt, (float*)d_out, nullptr, HH, HH, ffb2, x, active, nullptr, nullptr);
}

// round 14
// speedup vs baseline: 1.3691x; 1.1647x over previous
#include <cuda_runtime.h>
#include <cuda_fp16.h>
#include <cstdint>

#define NB 8
#define NN 2048
#define HH 512
#define MROWS (NB * NN)   // 16384

// ---------------------------------------------------------------------------
// Scratch (device globals — no allocation allowed)
// ---------------------------------------------------------------------------
__device__ float  g_x[MROWS * HH];                 // residual x (fp32)
__device__ __half g_xr[MROWS * HH];                // fp16 x2 (written by ff1)
__device__ float  g_h[MROWS * 1024];               // fp32 activations (layer-2 only)
__device__ __half g_hr[MROWS * 1024];              // fp16 activations
__device__ __half g_hwt[(size_t)1024 * MROWS];     // (h @ W)^T [Fo][MROWS], fp16
__device__ __half g_P[(size_t)MROWS * NN];         // unnormalized attention, fp16 (L1/L2)
__device__ __half g_wt[1024 * 1024];               // W^T [N][K], fp16
__device__ uint32_t g_adjT[MROWS * (NN / 32)];     // bit: valid(t, s), self-loop folded
__device__ float  g_ee[2 * MROWS];                 // [0..M) esrc, [M..2M) edst
__device__ float  g_f1[MROWS], g_f2[MROWS];        // per-source exp factors
__device__ float  g_qa[MROWS], g_qb[MROWS];        // per-target exp factors
__device__ float  g_rz[MROWS];                     // 1 / row-sum of P'
__device__ unsigned int g_smax_bits[NB];           // orderable-int max of esrc per batch
__device__ float  g_Weff[6 * HH];
__device__ float  g_beff[HH];
// Layer-0 rank-6 path (feature-major: g_feats[(b*8+q)*NN + s])
__device__ float  g_feats[NB * 8 * NN];
__device__ float  g_c6[MROWS * 8];                 // P-hat @ feats (rz-scaled), padded
__device__ float  g_W0eff[6 * 1024];               // Weff @ W0
__device__ float  g_b0w[1024];                     // beff @ W0
__device__ float  g_b0eff[1024];                   // beff @ W0 + gat_b0
__device__ float  g_v6[14];                        // [0..6) vsrc6, [6..12) vdst6, [12] c_src, [13] c_dst
__device__ float  g_l0part[8 * 7 * 1024];          // prep_l0a partials

// ---------------------------------------------------------------------------
// Helpers
// ---------------------------------------------------------------------------
__device__ __forceinline__ unsigned enc_ord(float f) {
    unsigned i = __float_as_uint(f);
    return (i & 0x80000000u) ? ~i : (i | 0x80000000u);
}
__device__ __forceinline__ float dec_ord(unsigned k) {
    unsigned i = (k & 0x80000000u) ? (k & 0x7FFFFFFFu) : ~k;
    return __uint_as_float(i);
}
__device__ __forceinline__ uint32_t smem_u32(const void* p) {
    uint32_t a;
    asm("{ .reg .u64 t; cvta.to.shared.u64 t, %1; cvt.u32.u64 %0, t; }" : "=r"(a) : "l"(p));
    return a;
}
__device__ __forceinline__ void mma16(float* c, const uint32_t* a, const uint32_t* b) {
    asm volatile(
        "mma.sync.aligned.m16n8k16.row.col.f32.f16.f16.f32 "
        "{%0,%1,%2,%3}, {%4,%5,%6,%7}, {%8,%9}, {%0,%1,%2,%3};"
        : "+f"(c[0]), "+f"(c[1]), "+f"(c[2]), "+f"(c[3])
        : "r"(a[0]), "r"(a[1]), "r"(a[2]), "r"(a[3]), "r"(b[0]), "r"(b[1]));
}
__device__ __forceinline__ void ldsm4(uint32_t* r, uint32_t addr) {
    asm volatile("ldmatrix.sync.aligned.m8n8.x4.shared.b16 {%0,%1,%2,%3}, [%4];"
                 : "=r"(r[0]), "=r"(r[1]), "=r"(r[2]), "=r"(r[3]) : "r"(addr));
}
#define CPA(dst, src) asm volatile("cp.async.cg.shared.global [%0], [%1], 16;" :: "r"(dst), "l"(src))
#define CPC() asm volatile("cp.async.commit_group;")
#define CPW(n) asm volatile("cp.async.wait_group %0;" :: "n"(n))

// k-major fp16 tile: 128 rows x 64 halfs (128 bytes/row). 16B chunk c4k = 0..7.
#define SOFFB(row, c4k) ((row) * 128 + ((((c4k)) ^ ((row) & 7)) << 4))

#define STAGE_BYTES 32768                 // A 16KB + B 16KB per stage (kt = 64)
#define SMEM_BYTES (3 * STAGE_BYTES)      // 96 KB, 2 CTAs/SM

// ---------------------------------------------------------------------------
// Unified fp16 tensor-core GEMM (fp32 accumulate).
// EPI 0: Ch^T[n][m] = h(acc); fused esrc/edst dots
// EPI 1: Ch = h(relu(acc*rz + bias))               (attention mid, batched)
// EPI 2: C = acc*rz + bias + X; Ch = h(C)          (attention last, batched)
// EPI 3: C = X + relu(acc + bias); Ch = h(C)       (ff1)
// EPI 4: C = (X + relu(acc + bias)) * act[row]     (ff2)
// ---------------------------------------------------------------------------
template <int EPI>
__global__ __launch_bounds__(256, 2) void gemm_tc(
    const __half* __restrict__ A, const __half* __restrict__ Bt,
    float* __restrict__ C, __half* __restrict__ Ch, int K, int N,
    const float* __restrict__ bias, const float* __restrict__ X,
    const float* __restrict__ act, const float* __restrict__ rz,
    float* __restrict__ ee)
{
    constexpr bool BATCHED = (EPI == 1 || EPI == 2);
    extern __shared__ char smc[];
    const uint32_t sbase = smem_u32(smc);
    const int tid = threadIdx.x;
    const int lane = tid & 31, wid = tid >> 5;

    int bx = blockIdx.x, by = blockIdx.y;
    {
        const int GX = gridDim.x;
        const int lin = by * GX + bx;
        const int grp = lin / (4 * GX);
        const int rem = lin - grp * 4 * GX;
        by = grp * 4 + (rem & 3);
        bx = rem >> 2;
    }
    const int m0 = by * 128, n0 = bx * 128;
    const int ws = wid >> 2, wcs = wid & 3;
    const int wm = ws * 64, wn = wcs * 32;

    int zoff = 0;
    if (BATCHED) zoff = blockIdx.z * NN;
    const __half* Ab = A + (size_t)zoff * K;
    const int ldb = BATCHED ? MROWS : K;
    const int kboff = BATCHED ? zoff : 0;
    float* Cb = (C != nullptr) ? C + (size_t)zoff * N : nullptr;
    __half* Chb = (Ch != nullptr && EPI != 0) ? Ch + (size_t)zoff * N : Ch;
    const float* Xb = (EPI >= 2) ? X + (size_t)zoff * N : nullptr;
    const float* rzb = BATCHED ? rz + zoff : nullptr;

    float acc[4][4][4];
#pragma unroll
    for (int i = 0; i < 4; i++)
#pragma unroll
        for (int j = 0; j < 4; j++)
#pragma unroll
            for (int q = 0; q < 4; q++) acc[i][j][q] = 0.f;

    const int row_l = tid >> 3, c4_l = tid & 7;

    auto issue = [&](int kt) {
        const int k0 = kt << 6;
        const uint32_t aB = sbase + (kt % 3) * STAGE_BYTES;
        const uint32_t bB = aB + 16384;
#pragma unroll
        for (int p = 0; p < 4; p++) {
            const int row = row_l + p * 32;
            const uint32_t so = SOFFB(row, c4_l);
            CPA(aB + so, Ab + (size_t)(m0 + row) * K + k0 + c4_l * 8);
            CPA(bB + so, Bt + (size_t)(n0 + row) * ldb + kboff + k0 + c4_l * 8);
        }
        CPC();
    };

    const int mA_row = lane & 15, mA_k = lane >> 4;
    const int nB_row = (lane & 7) + ((lane >> 4) << 3);
    const int nB_k = (lane >> 3) & 1;

    auto compute = [&](int stg) {
        const uint32_t aB = sbase + stg * STAGE_BYTES;
        const uint32_t bB = aB + 16384;
#pragma unroll
        for (int kk = 0; kk < 4; kk++) {
            uint32_t fa[4][4], fb[2][4];
#pragma unroll
            for (int mf = 0; mf < 4; mf++)
                ldsm4(fa[mf], aB + SOFFB(wm + mf * 16 + mA_row, kk * 2 + mA_k));
#pragma unroll
            for (int bp = 0; bp < 2; bp++)
                ldsm4(fb[bp], bB + SOFFB(wn + bp * 16 + nB_row, kk * 2 + nB_k));
#pragma unroll
            for (int mf = 0; mf < 4; mf++)
#pragma unroll
                for (int nf = 0; nf < 4; nf++)
                    mma16(acc[mf][nf], fa[mf], &fb[nf >> 1][(nf & 1) * 2]);
        }
    };

    const int nkt = K >> 6;
    issue(0);
    issue(1);
    for (int kt = 0; kt < nkt; kt++) {
        if (kt < nkt - 1) { CPW(1); } else { CPW(0); }
        __syncthreads();
        if (kt + 2 < nkt) issue(kt + 2);
        compute(kt % 3);
    }

#pragma unroll
    for (int mf = 0; mf < 4; mf++) {
#pragma unroll
        for (int rr = 0; rr < 2; rr++) {
            const int r = m0 + wm + mf * 16 + (lane >> 2) + rr * 8;
            float rzv = 1.f, actv = 1.f;
            if (BATCHED) rzv = rzb[r];
            if (EPI == 4) actv = act[r];
            float sE = 0.f, sD = 0.f;
#pragma unroll
            for (int nf = 0; nf < 4; nf++) {
                const int cc = n0 + wn + nf * 8 + (lane & 3) * 2;
                float v0 = acc[mf][nf][rr * 2 + 0];
                float v1 = acc[mf][nf][rr * 2 + 1];
                if (EPI == 0) {
                    const __half h0 = __float2half_rn(v0);
                    const __half h1 = __float2half_rn(v1);
                    Ch[(size_t)cc * MROWS + r]       = h0;
                    Ch[(size_t)(cc + 1) * MROWS + r] = h1;
                    const float c0 = __half2float(h0), c1 = __half2float(h1);
                    sE += c0 * bias[cc] + c1 * bias[cc + 1];
                    sD += c0 * X[cc] + c1 * X[cc + 1];
                } else {
                    if (BATCHED) { v0 *= rzv; v1 *= rzv; }
                    v0 += bias[cc]; v1 += bias[cc + 1];
                    if (EPI == 1) {
                        v0 = fmaxf(v0, 0.f); v1 = fmaxf(v1, 0.f);
                        *reinterpret_cast<__half2*>(Chb + (size_t)r * N + cc) =
                            __floats2half2_rn(v0, v1);
                    } else {
                        if (EPI == 2) {
                            const float* xr = Xb + (size_t)r * N + cc;
                            v0 += xr[0]; v1 += xr[1];
                        } else if (EPI == 3) {
                            const float* xr = Xb + (size_t)r * N + cc;
                            v0 = xr[0] + fmaxf(v0, 0.f); v1 = xr[1] + fmaxf(v1, 0.f);
                        } else if (EPI == 4) {
                            const float* xr = Xb + (size_t)r * N + cc;
                            v0 = (xr[0] + fmaxf(v0, 0.f)) * actv;
                            v1 = (xr[1] + fmaxf(v1, 0.f)) * actv;
                        }
                        *reinterpret_cast<float2*>(Cb + (size_t)r * N + cc) = make_float2(v0, v1);
                        if (EPI == 2 || EPI == 3) {
                            *reinterpret_cast<__half2*>(Chb + (size_t)r * N + cc) =
                                __floats2half2_rn(v0, v1);
                        }
                    }
                }
            }
            if (EPI == 0) {
                sE += __shfl_xor_sync(0xFFFFFFFFu, sE, 1);
                sE += __shfl_xor_sync(0xFFFFFFFFu, sE, 2);
                sD += __shfl_xor_sync(0xFFFFFFFFu, sD, 1);
                sD += __shfl_xor_sync(0xFFFFFFFFu, sD, 2);
                if ((lane & 3) == 0) {
                    atomicAdd(ee + r, sE);
                    atomicAdd(ee + MROWS + r, sD);
                }
            }
        }
    }
}

// ---------------------------------------------------------------------------
// 32x32 tiled transpose to fp16
// ---------------------------------------------------------------------------
__global__ void transpose_kernel(const float* __restrict__ in, __half* __restrict__ out,
                                 int R, int Cc)
{
    __shared__ float tile[32][33];
    int c0 = blockIdx.x * 32, r0 = blockIdx.y * 32;
    int x = threadIdx.x, y = threadIdx.y;
#pragma unroll
    for (int i = 0; i < 32; i += 8)
        tile[y + i][x] = in[(size_t)(r0 + y + i) * Cc + c0 + x];
    __syncthreads();
#pragma unroll
    for (int i = 0; i < 32; i += 8)
        out[(size_t)(c0 + y + i) * R + r0 + x] = __float2half_rn(tile[x][y + i]);
}

// ---------------------------------------------------------------------------
// adjT: bit s of word (b,t,s/32) = (adj[b][s][t]!=0) | (s==t)
// ---------------------------------------------------------------------------
__global__ __launch_bounds__(1024) void adjT_kernel(const int* __restrict__ adj)
{
    __shared__ int sa[32][33];
    const int b = blockIdx.z, t0 = blockIdx.y * 32, s0 = blockIdx.x * 32;
    const int w = threadIdx.x >> 5, lane = threadIdx.x & 31;
    sa[w][lane] = adj[((size_t)b * NN + s0 + w) * NN + t0 + lane];
    __syncthreads();
    const int t = t0 + w;
    uint32_t word = __ballot_sync(0xFFFFFFFFu, sa[lane][w] != 0);
    if (lane == 0) {
        if ((t >> 5) == (s0 >> 5)) word |= 1u << (t & 31);
        g_adjT[((size_t)b * NN + t) * (NN / 32) + (s0 >> 5)] = word;
    }
}

// ---------------------------------------------------------------------------
// Weff = emb_W1 @ emb_W2 ; beff = emb_b1 @ emb_W2 + emb_b2
// ---------------------------------------------------------------------------
__global__ void prep_weff_kernel(const float* __restrict__ W1, const float* __restrict__ b1,
                                 const float* __restrict__ W2, const float* __restrict__ b2)
{
    int j = blockIdx.x * 256 + threadIdx.x;
    if (j >= HH) return;
    float acc[6] = {0.f, 0.f, 0.f, 0.f, 0.f, 0.f};
    float bacc = b2[j];
    for (int k = 0; k < HH; k++) {
        float w2 = W2[k * HH + j];
        bacc += b1[k] * w2;
#pragma unroll
        for (int i = 0; i < 6; i++) acc[i] += W1[i * HH + k] * w2;
    }
#pragma unroll
    for (int i = 0; i < 6; i++) g_Weff[i * HH + j] = acc[i];
    g_beff[j] = bacc;
}

// ---------------------------------------------------------------------------
// prep_l0a two-stage: partials over 8 k-chunks, then reduce (+b0)
// ---------------------------------------------------------------------------
__global__ void prep_l0a_part(const float* __restrict__ W0)
{
    const int j = blockIdx.x * 256 + threadIdx.x;   // 0..1023
    const int kc = blockIdx.y;                      // 0..7
    float acc[6] = {0.f, 0.f, 0.f, 0.f, 0.f, 0.f};
    float bw = 0.f;
    const int k0 = kc * 64;
    for (int k = k0; k < k0 + 64; k++) {
        float w0 = W0[(size_t)k * 1024 + j];
        bw += g_beff[k] * w0;
#pragma unroll
        for (int i = 0; i < 6; i++) acc[i] += g_Weff[i * HH + k] * w0;
    }
#pragma unroll
    for (int i = 0; i < 6; i++) g_l0part[(kc * 7 + i) * 1024 + j] = acc[i];
    g_l0part[(kc * 7 + 6) * 1024 + j] = bw;
}

__global__ void prep_l0a_red(const float* __restrict__ b0)
{
    const int idx = blockIdx.x * 256 + threadIdx.x;   // < 7168
    const int q = idx >> 10, j = idx & 1023;
    float v = 0.f;
#pragma unroll
    for (int kc = 0; kc < 8; kc++) v += g_l0part[(kc * 7 + q) * 1024 + j];
    if (q < 6) {
        g_W0eff[q * 1024 + j] = v;
    } else {
        g_b0w[j] = v;
        g_b0eff[j] = v + b0[j];
    }
}

// ---------------------------------------------------------------------------
// vsrc6[i] = W0eff[i]·a_src; vdst6[i] = W0eff[i]·a_dst; c_src = b0w·a_src; c_dst
// ---------------------------------------------------------------------------
__global__ __launch_bounds__(256) void prep_l0b_kernel(const float* __restrict__ asrc,
                                                       const float* __restrict__ adst)
{
    __shared__ float red[14][256];
    const int t = threadIdx.x;
    float p[14];
#pragma unroll
    for (int q = 0; q < 14; q++) p[q] = 0.f;
    for (int j = t; j < 1024; j += 256) {
        float as = asrc[j], ad = adst[j], bw = g_b0w[j];
#pragma unroll
        for (int i = 0; i < 6; i++) {
            float w = g_W0eff[i * 1024 + j];
            p[i] += w * as;
            p[6 + i] += w * ad;
        }
        p[12] += bw * as;
        p[13] += bw * ad;
    }
#pragma unroll
    for (int q = 0; q < 14; q++) red[q][t] = p[q];
    __syncthreads();
    for (int s = 128; s; s >>= 1) {
        if (t < s) {
#pragma unroll
            for (int q = 0; q < 14; q++) red[q][t] += red[q][t + s];
        }
        __syncthreads();
    }
    if (t < 14) g_v6[t] = red[t][0];
}

// ---------------------------------------------------------------------------
// Features, feature-major per batch: g_feats[(b*8+q)*NN + s]
// ---------------------------------------------------------------------------
__global__ void feats_kernel(const float* __restrict__ arr, const float* __restrict__ dep,
                             const float* __restrict__ hard,
                             const float* __restrict__ ts, const float* __restrict__ tt)
{
    int row = blockIdx.x * 256 + threadIdx.x;
    int b = row >> 11;
    int s = row & (NN - 1);
    float t = ts[b], T = tt[b];
    float ar = arr[row], de = dep[row];
    float f[6];
    f[0] = (t - ar) / (de - ar);
    f[1] = t / T;
    f[2] = fmodf(f[1], 2.f);
    f[3] = fmodf(f[1], 4.f);
    f[4] = fmodf(f[1], 7.f);
    f[5] = hard[row];
    float* base = g_feats + (size_t)b * 8 * NN + s;
#pragma unroll
    for (int q = 0; q < 6; q++) base[q * NN] = f[q];
}

// ---------------------------------------------------------------------------
// Embedding from precomputed feats: x = feats @ Weff + beff (fp32 only)
// ---------------------------------------------------------------------------
__global__ void embed_kernel()
{
    int idx = blockIdx.x * 256 + threadIdx.x;
    int j = idx & (HH - 1);
    int row = idx >> 9;
    int b = row >> 11;
    int s = row & (NN - 1);
    const float* fb = g_feats + (size_t)b * 8 * NN + s;
    float acc = g_beff[j];
#pragma unroll
    for (int i = 0; i < 6; i++) acc += fb[i * NN] * g_Weff[i * HH + j];
    g_x[idx] = acc;
}

// ---------------------------------------------------------------------------
// Layer-0 e_src/e_dst via rank-6 + fused per-batch smax
// (each 256-row block lies entirely within one batch)
// ---------------------------------------------------------------------------
__global__ __launch_bounds__(256) void l0_e_kernel()
{
    int row = blockIdx.x * 256 + threadIdx.x;
    int b = row >> 11;
    int s = row & (NN - 1);
    const float* base = g_feats + (size_t)b * 8 * NN + s;
    float es = g_v6[12], ed = g_v6[13];
#pragma unroll
    for (int i = 0; i < 6; i++) {
        float fv = base[i * NN];
        es += fv * g_v6[i];
        ed += fv * g_v6[6 + i];
    }
    g_ee[row] = es;
    g_ee[MROWS + row] = ed;
    // fused per-batch max of esrc
    float v = es;
#pragma unroll
    for (int off = 16; off; off >>= 1)
        v = fmaxf(v, __shfl_xor_sync(0xFFFFFFFFu, v, off));
    __shared__ float red[8];
    const int w = threadIdx.x >> 5, l = threadIdx.x & 31;
    if (l == 0) red[w] = v;
    __syncthreads();
    if (threadIdx.x == 0) {
        float m = red[0];
#pragma unroll
        for (int q = 1; q < 8; q++) m = fmaxf(m, red[q]);
        atomicMax(&g_smax_bits[b], enc_ord(m));
    }
}

// ---------------------------------------------------------------------------
// Reset per-batch smax + zero ee
// ---------------------------------------------------------------------------
__global__ void zero_ee2_kernel()
{
    int i = blockIdx.x * 256 + threadIdx.x;
    if (i < 2 * MROWS) g_ee[i] = 0.f;
    if (i < NB) g_smax_bits[i] = 0x007FFFFFu;  // enc(-inf)
}

// ---------------------------------------------------------------------------
// Per-batch max of esrc -> g_smax_bits (L1/L2 after gemm0 fused dots)
// ---------------------------------------------------------------------------
__global__ __launch_bounds__(256) void smax_kernel()
{
    const int i = blockIdx.x * 256 + threadIdx.x;
    float v = g_ee[i];
#pragma unroll
    for (int off = 16; off; off >>= 1)
        v = fmaxf(v, __shfl_xor_sync(0xFFFFFFFFu, v, off));
    __shared__ float red[8];
    const int w = threadIdx.x >> 5, l = threadIdx.x & 31;
    if (l == 0) red[w] = v;
    __syncthreads();
    if (threadIdx.x == 0) {
        float m = red[0];
#pragma unroll
        for (int q = 1; q < 8; q++) m = fmaxf(m, red[q]);
        atomicMax(&g_smax_bits[i >> 11], enc_ord(m));
    }
}

// ---------------------------------------------------------------------------
// Per-node exp factors (all exponents <= 0 -> no overflow)
// ---------------------------------------------------------------------------
__global__ void nodeprep_kernel()
{
    int t = blockIdx.x * 256 + threadIdx.x;
    int b = t >> 11;
    float sm = dec_ord(g_smax_bits[b]);
    float es = g_ee[t], ed = g_ee[MROWS + t];
    g_f1[t] = __expf(es - sm);
    g_f2[t] = __expf(0.2f * (es - sm));
    float u = ed + sm;
    float mh = fmaxf(u, 0.2f * u);
    g_qa[t] = __expf(u - mh);
    g_qb[t] = __expf(0.2f * u - mh);
}

// ---------------------------------------------------------------------------
// L0 fused pgen: generate P row in registers, accumulate Z and P@feats.
// Feature-major smem [6][2048] -> conflict-free float4 loads.
// ---------------------------------------------------------------------------
__global__ __launch_bounds__(256) void pgen_l0_kernel()
{
    extern __shared__ float sf[];   // [6][2048] feats for this block's batch
    const int tid = threadIdx.x;
    const int wid = tid >> 5, lane = tid & 31;
    const int t = blockIdx.x * 8 + wid;
    const int b = t >> 11;
    {
        const float4* src = reinterpret_cast<const float4*>(g_feats + (size_t)b * 8 * NN);
        float4* dst = reinterpret_cast<float4*>(sf);
        for (int i = tid; i < 6 * NN / 4; i += 256) dst[i] = src[i];
    }
    __syncthreads();

    const float qa = g_qa[t], qb = g_qb[t];
    const uint32_t* wrow = g_adjT + (size_t)t * (NN / 32);
    const float* f1 = g_f1 + b * NN;
    const float* f2 = g_f2 + b * NN;
    float sum = 0.f;
    float c[6] = {0.f, 0.f, 0.f, 0.f, 0.f, 0.f};
#pragma unroll 2
    for (int i = 0; i < 16; i++) {
        const int s = i * 128 + lane * 4;
        const uint32_t w = wrow[s >> 5];
        const uint32_t sh = s & 31;
        float4 x1 = *reinterpret_cast<const float4*>(f1 + s);
        float4 x2 = *reinterpret_cast<const float4*>(f2 + s);
        float o0 = ((w >> (sh + 0)) & 1u) ? fmaxf(qa * x1.x, qb * x2.x) : 0.f;
        float o1 = ((w >> (sh + 1)) & 1u) ? fmaxf(qa * x1.y, qb * x2.y) : 0.f;
        float o2 = ((w >> (sh + 2)) & 1u) ? fmaxf(qa * x1.z, qb * x2.z) : 0.f;
        float o3 = ((w >> (sh + 3)) & 1u) ? fmaxf(qa * x1.w, qb * x2.w) : 0.f;
        sum += (o0 + o1) + (o2 + o3);
#pragma unroll
        for (int q = 0; q < 6; q++) {
            const float4 fq = *reinterpret_cast<const float4*>(sf + q * NN + s);
            c[q] += o0 * fq.x + o1 * fq.y + o2 * fq.z + o3 * fq.w;
        }
    }
#pragma unroll
    for (int off = 16; off; off >>= 1) {
        sum += __shfl_xor_sync(0xFFFFFFFFu, sum, off);
#pragma unroll
        for (int q = 0; q < 6; q++) c[q] += __shfl_xor_sync(0xFFFFFFFFu, c[q], off);
    }
    if (lane == 0) {
        const float rzv = 1.f / fmaxf(sum, 1e-30f);
        g_rz[t] = rzv;
        float* co = g_c6 + t * 8;
#pragma unroll
        for (int q = 0; q < 6; q++) co[q] = c[q] * rzv;
    }
}

// ---------------------------------------------------------------------------
// L0 output: hr[t][j] = h(relu( c6[t]·W0eff[:,j] + b0eff[j] ))
// ---------------------------------------------------------------------------
__global__ void l0_out_kernel()
{
    int idx = blockIdx.x * 256 + threadIdx.x;     // < MROWS*1024
    int j = idx & 1023;
    int row = idx >> 10;
    const float* c = g_c6 + row * 8;
    float acc = g_b0eff[j];
#pragma unroll
    for (int i = 0; i < 6; i++) acc += c[i] * g_W0eff[i * 1024 + j];
    g_hr[(size_t)row * 1024 + j] = __float2half_rn(fmaxf(acc, 0.f));
}

// ---------------------------------------------------------------------------
// Materialize P' (fp16) + fused row-sum -> g_rz (L1/L2). One warp per row.
// ---------------------------------------------------------------------------
__global__ __launch_bounds__(256) void pgen_kernel()
{
    const int wid = threadIdx.x >> 5, lane = threadIdx.x & 31;
    const int t = blockIdx.x * 8 + wid;
    const int b = t >> 11;
    const float qa = g_qa[t], qb = g_qb[t];
    const uint32_t* wrow = g_adjT + (size_t)t * (NN / 32);
    const float* f1 = g_f1 + b * NN;
    const float* f2 = g_f2 + b * NN;
    __half* Prow = g_P + (size_t)t * NN;
    float sum = 0.f;
#pragma unroll 4
    for (int i = 0; i < 16; i++) {
        const int s = i * 128 + lane * 4;
        const uint32_t w = wrow[s >> 5];
        const uint32_t sh = s & 31;
        float4 x1 = *reinterpret_cast<const float4*>(f1 + s);
        float4 x2 = *reinterpret_cast<const float4*>(f2 + s);
        float o0 = ((w >> (sh + 0)) & 1u) ? fmaxf(qa * x1.x, qb * x2.x) : 0.f;
        float o1 = ((w >> (sh + 1)) & 1u) ? fmaxf(qa * x1.y, qb * x2.y) : 0.f;
        float o2 = ((w >> (sh + 2)) & 1u) ? fmaxf(qa * x1.z, qb * x2.z) : 0.f;
        float o3 = ((w >> (sh + 3)) & 1u) ? fmaxf(qa * x1.w, qb * x2.w) : 0.f;
        __half2 p01 = __floats2half2_rn(o0, o1);
        __half2 p23 = __floats2half2_rn(o2, o3);
        float2 q01 = __half22float2(p01);
        float2 q23 = __half22float2(p23);
        sum += (q01.x + q01.y) + (q23.x + q23.y);
        *reinterpret_cast<__half2*>(Prow + s)     = p01;
        *reinterpret_cast<__half2*>(Prow + s + 2) = p23;
    }
#pragma unroll
    for (int off = 16; off; off >>= 1) sum += __shfl_xor_sync(0xFFFFFFFFu, sum, off);
    if (lane == 0) g_rz[t] = 1.f / fmaxf(sum, 1e-30f);
}

// ---------------------------------------------------------------------------
// Host launcher
// ---------------------------------------------------------------------------
extern "C" void kernel_launch(void* const* d_in, const int* in_sizes, int n_in,
                              void* d_out, int out_size)
{
    const int*   adj      = (const int*)d_in[0];
    const float* arrivals = (const float*)d_in[1];
    const float* depart   = (const float*)d_in[2];
    const float* hard     = (const float*)d_in[3];
    const float* active   = (const float*)d_in[4];
    const float* timestep = (const float*)d_in[5];
    const float* totalts  = (const float*)d_in[6];
    const float* embW1 = (const float*)d_in[7];
    const float* embb1 = (const float*)d_in[8];
    const float* embW2 = (const float*)d_in[9];
    const float* embb2 = (const float*)d_in[10];
    const float* gatW[3]    = {(const float*)d_in[11], (const float*)d_in[15], (const float*)d_in[19]};
    const float* gatAsrc[3] = {(const float*)d_in[12], (const float*)d_in[16], (const float*)d_in[20]};
    const float* gatAdst[3] = {(const float*)d_in[13], (const float*)d_in[17], (const float*)d_in[21]};
    const float* gatB[3]    = {(const float*)d_in[14], (const float*)d_in[18], (const float*)d_in[22]};
    const float* ffW1 = (const float*)d_in[23];
    const float* ffb1 = (const float*)d_in[24];
    const float* ffW2 = (const float*)d_in[25];
    const float* ffb2 = (const float*)d_in[26];

    float *x, *h, *rz, *ee;
    __half *xr, *hr, *hwt, *P, *wt;
    cudaGetSymbolAddress((void**)&x,   g_x);
    cudaGetSymbolAddress((void**)&xr,  g_xr);
    cudaGetSymbolAddress((void**)&h,   g_h);
    cudaGetSymbolAddress((void**)&hr,  g_hr);
    cudaGetSymbolAddress((void**)&hwt, g_hwt);
    cudaGetSymbolAddress((void**)&P,   g_P);
    cudaGetSymbolAddress((void**)&rz,  g_rz);
    cudaGetSymbolAddress((void**)&wt,  g_wt);
    cudaGetSymbolAddress((void**)&ee,  g_ee);

    static int smem_set = 0;
    if (!smem_set) {
        cudaFuncSetAttribute(gemm_tc<0>, cudaFuncAttributeMaxDynamicSharedMemorySize, SMEM_BYTES);
        cudaFuncSetAttribute(gemm_tc<1>, cudaFuncAttributeMaxDynamicSharedMemorySize, SMEM_BYTES);
        cudaFuncSetAttribute(gemm_tc<2>, cudaFuncAttributeMaxDynamicSharedMemorySize, SMEM_BYTES);
        cudaFuncSetAttribute(gemm_tc<3>, cudaFuncAttributeMaxDynamicSharedMemorySize, SMEM_BYTES);
        cudaFuncSetAttribute(gemm_tc<4>, cudaFuncAttributeMaxDynamicSharedMemorySize, SMEM_BYTES);
        cudaFuncSetAttribute(pgen_l0_kernel, cudaFuncAttributeMaxDynamicSharedMemorySize, 6 * NN * 4);
        smem_set = 1;
    }

    // Prep + features + embedding + adjacency
    prep_weff_kernel<<<2, 256>>>(embW1, embb1, embW2, embb2);
    feats_kernel<<<MROWS / 256, 256>>>(arrivals, depart, hard, timestep, totalts);
    prep_l0a_part<<<dim3(4, 8), 256>>>(gatW[0]);
    prep_l0a_red<<<28, 256>>>(gatB[0]);
    prep_l0b_kernel<<<1, 256>>>(gatAsrc[0], gatAdst[0]);
    embed_kernel<<<(MROWS * HH) / 256, 256>>>();
    adjT_kernel<<<dim3(NN / 32, NN / 32, NB), 1024>>>(adj);

    // ---- Layer 0: rank-6 collapsed attention ----
    zero_ee2_kernel<<<(2 * MROWS) / 256, 256>>>();   // resets smax
    l0_e_kernel<<<MROWS / 256, 256>>>();             // e + fused smax
    nodeprep_kernel<<<MROWS / 256, 256>>>();
    pgen_l0_kernel<<<MROWS / 8, 256, 6 * NN * 4>>>();
    l0_out_kernel<<<(MROWS * 1024) / 256, 256>>>();

    // ---- Layers 1, 2: dense path ----
    const int Kin[3] = {0, 1024, 1024};
    const int Fo[3]  = {0, 1024, HH};
    const dim3 tblk(32, 8);
    for (int l = 1; l < 3; l++) {
        transpose_kernel<<<dim3(Fo[l] / 32, Kin[l] / 32), tblk>>>(gatW[l], wt, Kin[l], Fo[l]);
        zero_ee2_kernel<<<(2 * MROWS) / 256, 256>>>();
        gemm_tc<0><<<dim3(Fo[l] / 128, MROWS / 128), 256, SMEM_BYTES>>>(
            hr, wt, nullptr, hwt, Kin[l], Fo[l], gatAsrc[l], gatAdst[l], nullptr, nullptr, ee);
        smax_kernel<<<MROWS / 256, 256>>>();
        nodeprep_kernel<<<MROWS / 256, 256>>>();
        pgen_kernel<<<MROWS / 8, 256>>>();
        if (l < 2) {
            gemm_tc<1><<<dim3(Fo[l] / 128, NN / 128, NB), 256, SMEM_BYTES>>>(
                P, hwt, nullptr, hr, NN, Fo[l], gatB[l], nullptr, nullptr, rz, nullptr);
        } else {
            gemm_tc<2><<<dim3(Fo[l] / 128, NN / 128, NB), 256, SMEM_BYTES>>>(
                P, hwt, h, hr, NN, Fo[l], gatB[l], x, nullptr, rz, nullptr);
        }
    }

    // ff1: x2 = x1 + relu(x1 @ W1 + b1)
    transpose_kernel<<<dim3(HH / 32, HH / 32), tblk>>>(ffW1, wt, HH, HH);
    gemm_tc<3><<<dim3(HH / 128, MROWS / 128), 256, SMEM_BYTES>>>(
        hr, wt, x, xr, HH, HH, ffb1, h, nullptr, nullptr, nullptr);
    // ff2: out = (x2 + relu(x2 @ W2 + b2)) * active
    transpose_kernel<<<dim3(HH / 32, HH / 32), tblk>>>(ffW2, wt, HH, HH);
    gemm_tc<4><<<dim3(HH / 128, MROWS / 128), 256, SMEM_BYTES>>>(
        xr, wt, (float*)d_out, nullptr, HH, HH, ffb2, x, active, nullptr, nullptr);
}

// round 15
// speedup vs baseline: 1.3692x; 1.0001x over previous
#include <cuda_runtime.h>
#include <cuda_fp16.h>
#include <cstdint>

#define NB 8
#define NN 2048
#define HH 512
#define MROWS (NB * NN)   // 16384

// ---------------------------------------------------------------------------
// Scratch (device globals — no allocation allowed)
// ---------------------------------------------------------------------------
__device__ float  g_x[MROWS * HH];                 // residual x (fp32)
__device__ __half g_xr[MROWS * HH];                // fp16 x2 (written by ff1)
__device__ float  g_h[MROWS * 1024];               // fp32 activations (layer-2 only)
__device__ __half g_hr[MROWS * 1024];              // fp16 activations
__device__ __half g_hwt[(size_t)1024 * MROWS];     // (h @ W)^T [Fo][MROWS], fp16
__device__ __half g_P[(size_t)MROWS * NN];         // unnormalized attention, fp16 (L1/L2)
__device__ __half g_wt[1024 * 1024];               // W^T [N][K], fp16
__device__ uint32_t g_adjT[MROWS * (NN / 32)];     // bit: valid(t, s), self-loop folded
__device__ float  g_ee[2 * MROWS];                 // [0..M) esrc, [M..2M) edst
__device__ float  g_f1[MROWS], g_f2[MROWS];        // per-source exp factors
__device__ float  g_qa[MROWS], g_qb[MROWS];        // per-target exp factors
__device__ float  g_rz[MROWS];                     // 1 / row-sum of P'
__device__ unsigned int g_smax_bits[NB];           // orderable-int max of esrc per batch
__device__ float  g_Weff[6 * HH];
__device__ float  g_beff[HH];
// Layer-0 rank-6 path (feature-major: g_feats[(b*8+q)*NN + s])
__device__ float  g_feats[NB * 8 * NN];
__device__ float  g_c6[MROWS * 8];                 // P-hat @ feats (rz-scaled), padded
__device__ float  g_W0eff[6 * 1024];               // Weff @ W0
__device__ float  g_b0w[1024];                     // beff @ W0
__device__ float  g_b0eff[1024];                   // beff @ W0 + gat_b0
__device__ float  g_v6[14];                        // [0..6) vsrc6, [6..12) vdst6, [12] c_src, [13] c_dst
__device__ float  g_l0part[8 * 7 * 1024];          // prep_l0a partials

// ---------------------------------------------------------------------------
// Helpers
// ---------------------------------------------------------------------------
__device__ __forceinline__ unsigned enc_ord(float f) {
    unsigned i = __float_as_uint(f);
    return (i & 0x80000000u) ? ~i : (i | 0x80000000u);
}
__device__ __forceinline__ float dec_ord(unsigned k) {
    unsigned i = (k & 0x80000000u) ? (k & 0x7FFFFFFFu) : ~k;
    return __uint_as_float(i);
}
__device__ __forceinline__ uint32_t smem_u32(const void* p) {
    uint32_t a;
    asm("{ .reg .u64 t; cvta.to.shared.u64 t, %1; cvt.u32.u64 %0, t; }" : "=r"(a) : "l"(p));
    return a;
}
__device__ __forceinline__ void mma16(float* c, const uint32_t* a, const uint32_t* b) {
    asm volatile(
        "mma.sync.aligned.m16n8k16.row.col.f32.f16.f16.f32 "
        "{%0,%1,%2,%3}, {%4,%5,%6,%7}, {%8,%9}, {%0,%1,%2,%3};"
        : "+f"(c[0]), "+f"(c[1]), "+f"(c[2]), "+f"(c[3])
        : "r"(a[0]), "r"(a[1]), "r"(a[2]), "r"(a[3]), "r"(b[0]), "r"(b[1]));
}
__device__ __forceinline__ void ldsm4(uint32_t* r, uint32_t addr) {
    asm volatile("ldmatrix.sync.aligned.m8n8.x4.shared.b16 {%0,%1,%2,%3}, [%4];"
                 : "=r"(r[0]), "=r"(r[1]), "=r"(r[2]), "=r"(r[3]) : "r"(addr));
}
#define CPA(dst, src) asm volatile("cp.async.cg.shared.global [%0], [%1], 16;" :: "r"(dst), "l"(src))
#define CPC() asm volatile("cp.async.commit_group;")
#define CPW(n) asm volatile("cp.async.wait_group %0;" :: "n"(n))

// k-major fp16 tile: 128 rows x 64 halfs (128 bytes/row). 16B chunk c4k = 0..7.
#define SOFFB(row, c4k) ((row) * 128 + ((((c4k)) ^ ((row) & 7)) << 4))

#define STAGE_BYTES 32768                 // A 16KB + B 16KB per stage (kt = 64)
#define SMEM_BYTES (3 * STAGE_BYTES)      // 96 KB, 2 CTAs/SM

// ---------------------------------------------------------------------------
// Unified fp16 tensor-core GEMM (fp32 accumulate).
// EPI 0: Ch^T[n][m] = h(acc); fused esrc/edst dots
// EPI 1: Ch = h(relu(acc*rz + bias))               (attention mid, batched)
// EPI 2: C = acc*rz + bias + X; Ch = h(C)          (attention last, batched)
// EPI 3: C = X + relu(acc + bias); Ch = h(C)       (ff1)
// EPI 4: C = (X + relu(acc + bias)) * act[row]     (ff2)
// ---------------------------------------------------------------------------
template <int EPI>
__global__ __launch_bounds__(256, 2) void gemm_tc(
    const __half* __restrict__ A, const __half* __restrict__ Bt,
    float* __restrict__ C, __half* __restrict__ Ch, int K, int N,
    const float* __restrict__ bias, const float* __restrict__ X,
    const float* __restrict__ act, const float* __restrict__ rz,
    float* __restrict__ ee)
{
    constexpr bool BATCHED = (EPI == 1 || EPI == 2);
    extern __shared__ char smc[];
    const uint32_t sbase = smem_u32(smc);
    const int tid = threadIdx.x;
    const int lane = tid & 31, wid = tid >> 5;

    int bx = blockIdx.x, by = blockIdx.y;
    {
        const int GX = gridDim.x;
        const int lin = by * GX + bx;
        const int grp = lin / (4 * GX);
        const int rem = lin - grp * 4 * GX;
        by = grp * 4 + (rem & 3);
        bx = rem >> 2;
    }
    const int m0 = by * 128, n0 = bx * 128;
    const int ws = wid >> 2, wcs = wid & 3;
    const int wm = ws * 64, wn = wcs * 32;

    int zoff = 0;
    if (BATCHED) zoff = blockIdx.z * NN;
    const __half* Ab = A + (size_t)zoff * K;
    const int ldb = BATCHED ? MROWS : K;
    const int kboff = BATCHED ? zoff : 0;
    float* Cb = (C != nullptr) ? C + (size_t)zoff * N : nullptr;
    __half* Chb = (Ch != nullptr && EPI != 0) ? Ch + (size_t)zoff * N : Ch;
    const float* Xb = (EPI >= 2) ? X + (size_t)zoff * N : nullptr;
    const float* rzb = BATCHED ? rz + zoff : nullptr;

    float acc[4][4][4];
#pragma unroll
    for (int i = 0; i < 4; i++)
#pragma unroll
        for (int j = 0; j < 4; j++)
#pragma unroll
            for (int q = 0; q < 4; q++) acc[i][j][q] = 0.f;

    const int row_l = tid >> 3, c4_l = tid & 7;

    auto issue = [&](int kt) {
        const int k0 = kt << 6;
        const uint32_t aB = sbase + (kt % 3) * STAGE_BYTES;
        const uint32_t bB = aB + 16384;
#pragma unroll
        for (int p = 0; p < 4; p++) {
            const int row = row_l + p * 32;
            const uint32_t so = SOFFB(row, c4_l);
            CPA(aB + so, Ab + (size_t)(m0 + row) * K + k0 + c4_l * 8);
            CPA(bB + so, Bt + (size_t)(n0 + row) * ldb + kboff + k0 + c4_l * 8);
        }
        CPC();
    };

    const int mA_row = lane & 15, mA_k = lane >> 4;
    const int nB_row = (lane & 7) + ((lane >> 4) << 3);
    const int nB_k = (lane >> 3) & 1;

    auto compute = [&](int stg) {
        const uint32_t aB = sbase + stg * STAGE_BYTES;
        const uint32_t bB = aB + 16384;
#pragma unroll
        for (int kk = 0; kk < 4; kk++) {
            uint32_t fa[4][4], fb[2][4];
#pragma unroll
            for (int mf = 0; mf < 4; mf++)
                ldsm4(fa[mf], aB + SOFFB(wm + mf * 16 + mA_row, kk * 2 + mA_k));
#pragma unroll
            for (int bp = 0; bp < 2; bp++)
                ldsm4(fb[bp], bB + SOFFB(wn + bp * 16 + nB_row, kk * 2 + nB_k));
#pragma unroll
            for (int mf = 0; mf < 4; mf++)
#pragma unroll
                for (int nf = 0; nf < 4; nf++)
                    mma16(acc[mf][nf], fa[mf], &fb[nf >> 1][(nf & 1) * 2]);
        }
    };

    const int nkt = K >> 6;
    issue(0);
    issue(1);
    for (int kt = 0; kt < nkt; kt++) {
        if (kt < nkt - 1) { CPW(1); } else { CPW(0); }
        __syncthreads();
        if (kt + 2 < nkt) issue(kt + 2);
        compute(kt % 3);
    }

#pragma unroll
    for (int mf = 0; mf < 4; mf++) {
#pragma unroll
        for (int rr = 0; rr < 2; rr++) {
            const int r = m0 + wm + mf * 16 + (lane >> 2) + rr * 8;
            float rzv = 1.f, actv = 1.f;
            if (BATCHED) rzv = rzb[r];
            if (EPI == 4) actv = act[r];
            float sE = 0.f, sD = 0.f;
#pragma unroll
            for (int nf = 0; nf < 4; nf++) {
                const int cc = n0 + wn + nf * 8 + (lane & 3) * 2;
                float v0 = acc[mf][nf][rr * 2 + 0];
                float v1 = acc[mf][nf][rr * 2 + 1];
                if (EPI == 0) {
                    const __half h0 = __float2half_rn(v0);
                    const __half h1 = __float2half_rn(v1);
                    Ch[(size_t)cc * MROWS + r]       = h0;
                    Ch[(size_t)(cc + 1) * MROWS + r] = h1;
                    const float c0 = __half2float(h0), c1 = __half2float(h1);
                    sE += c0 * bias[cc] + c1 * bias[cc + 1];
                    sD += c0 * X[cc] + c1 * X[cc + 1];
                } else {
                    if (BATCHED) { v0 *= rzv; v1 *= rzv; }
                    v0 += bias[cc]; v1 += bias[cc + 1];
                    if (EPI == 1) {
                        v0 = fmaxf(v0, 0.f); v1 = fmaxf(v1, 0.f);
                        *reinterpret_cast<__half2*>(Chb + (size_t)r * N + cc) =
                            __floats2half2_rn(v0, v1);
                    } else {
                        if (EPI == 2) {
                            const float* xr = Xb + (size_t)r * N + cc;
                            v0 += xr[0]; v1 += xr[1];
                        } else if (EPI == 3) {
                            const float* xr = Xb + (size_t)r * N + cc;
                            v0 = xr[0] + fmaxf(v0, 0.f); v1 = xr[1] + fmaxf(v1, 0.f);
                        } else if (EPI == 4) {
                            const float* xr = Xb + (size_t)r * N + cc;
                            v0 = (xr[0] + fmaxf(v0, 0.f)) * actv;
                            v1 = (xr[1] + fmaxf(v1, 0.f)) * actv;
                        }
                        *reinterpret_cast<float2*>(Cb + (size_t)r * N + cc) = make_float2(v0, v1);
                        if (EPI == 2 || EPI == 3) {
                            *reinterpret_cast<__half2*>(Chb + (size_t)r * N + cc) =
                                __floats2half2_rn(v0, v1);
                        }
                    }
                }
            }
            if (EPI == 0) {
                sE += __shfl_xor_sync(0xFFFFFFFFu, sE, 1);
                sE += __shfl_xor_sync(0xFFFFFFFFu, sE, 2);
                sD += __shfl_xor_sync(0xFFFFFFFFu, sD, 1);
                sD += __shfl_xor_sync(0xFFFFFFFFu, sD, 2);
                if ((lane & 3) == 0) {
                    atomicAdd(ee + r, sE);
                    atomicAdd(ee + MROWS + r, sD);
                }
            }
        }
    }
}

// ---------------------------------------------------------------------------
// 32x32 tiled transpose to fp16
// ---------------------------------------------------------------------------
__global__ void transpose_kernel(const float* __restrict__ in, __half* __restrict__ out,
                                 int R, int Cc)
{
    __shared__ float tile[32][33];
    int c0 = blockIdx.x * 32, r0 = blockIdx.y * 32;
    int x = threadIdx.x, y = threadIdx.y;
#pragma unroll
    for (int i = 0; i < 32; i += 8)
        tile[y + i][x] = in[(size_t)(r0 + y + i) * Cc + c0 + x];
    __syncthreads();
#pragma unroll
    for (int i = 0; i < 32; i += 8)
        out[(size_t)(c0 + y + i) * R + r0 + x] = __float2half_rn(tile[x][y + i]);
}

// ---------------------------------------------------------------------------
// adjT: bit s of word (b,t,s/32) = (adj[b][s][t]!=0) | (s==t)
// ---------------------------------------------------------------------------
__global__ __launch_bounds__(1024) void adjT_kernel(const int* __restrict__ adj)
{
    __shared__ int sa[32][33];
    const int b = blockIdx.z, t0 = blockIdx.y * 32, s0 = blockIdx.x * 32;
    const int w = threadIdx.x >> 5, lane = threadIdx.x & 31;
    sa[w][lane] = adj[((size_t)b * NN + s0 + w) * NN + t0 + lane];
    __syncthreads();
    const int t = t0 + w;
    uint32_t word = __ballot_sync(0xFFFFFFFFu, sa[lane][w] != 0);
    if (lane == 0) {
        if ((t >> 5) == (s0 >> 5)) word |= 1u << (t & 31);
        g_adjT[((size_t)b * NN + t) * (NN / 32) + (s0 >> 5)] = word;
    }
}

// ---------------------------------------------------------------------------
// Weff = emb_W1 @ emb_W2 ; beff = emb_b1 @ emb_W2 + emb_b2
// ---------------------------------------------------------------------------
__global__ void prep_weff_kernel(const float* __restrict__ W1, const float* __restrict__ b1,
                                 const float* __restrict__ W2, const float* __restrict__ b2)
{
    int j = blockIdx.x * 256 + threadIdx.x;
    if (j >= HH) return;
    float acc[6] = {0.f, 0.f, 0.f, 0.f, 0.f, 0.f};
    float bacc = b2[j];
    for (int k = 0; k < HH; k++) {
        float w2 = W2[k * HH + j];
        bacc += b1[k] * w2;
#pragma unroll
        for (int i = 0; i < 6; i++) acc[i] += W1[i * HH + k] * w2;
    }
#pragma unroll
    for (int i = 0; i < 6; i++) g_Weff[i * HH + j] = acc[i];
    g_beff[j] = bacc;
}

// ---------------------------------------------------------------------------
// prep_l0a two-stage: partials over 8 k-chunks, then reduce (+b0)
// ---------------------------------------------------------------------------
__global__ void prep_l0a_part(const float* __restrict__ W0)
{
    const int j = blockIdx.x * 256 + threadIdx.x;   // 0..1023
    const int kc = blockIdx.y;                      // 0..7
    float acc[6] = {0.f, 0.f, 0.f, 0.f, 0.f, 0.f};
    float bw = 0.f;
    const int k0 = kc * 64;
    for (int k = k0; k < k0 + 64; k++) {
        float w0 = W0[(size_t)k * 1024 + j];
        bw += g_beff[k] * w0;
#pragma unroll
        for (int i = 0; i < 6; i++) acc[i] += g_Weff[i * HH + k] * w0;
    }
#pragma unroll
    for (int i = 0; i < 6; i++) g_l0part[(kc * 7 + i) * 1024 + j] = acc[i];
    g_l0part[(kc * 7 + 6) * 1024 + j] = bw;
}

__global__ void prep_l0a_red(const float* __restrict__ b0)
{
    const int idx = blockIdx.x * 256 + threadIdx.x;   // < 7168
    const int q = idx >> 10, j = idx & 1023;
    float v = 0.f;
#pragma unroll
    for (int kc = 0; kc < 8; kc++) v += g_l0part[(kc * 7 + q) * 1024 + j];
    if (q < 6) {
        g_W0eff[q * 1024 + j] = v;
    } else {
        g_b0w[j] = v;
        g_b0eff[j] = v + b0[j];
    }
}

// ---------------------------------------------------------------------------
// vsrc6[i] = W0eff[i]·a_src; vdst6[i] = W0eff[i]·a_dst; c_src = b0w·a_src; c_dst
// ---------------------------------------------------------------------------
__global__ __launch_bounds__(256) void prep_l0b_kernel(const float* __restrict__ asrc,
                                                       const float* __restrict__ adst)
{
    __shared__ float red[14][256];
    const int t = threadIdx.x;
    float p[14];
#pragma unroll
    for (int q = 0; q < 14; q++) p[q] = 0.f;
    for (int j = t; j < 1024; j += 256) {
        float as = asrc[j], ad = adst[j], bw = g_b0w[j];
#pragma unroll
        for (int i = 0; i < 6; i++) {
            float w = g_W0eff[i * 1024 + j];
            p[i] += w * as;
            p[6 + i] += w * ad;
        }
        p[12] += bw * as;
        p[13] += bw * ad;
    }
#pragma unroll
    for (int q = 0; q < 14; q++) red[q][t] = p[q];
    __syncthreads();
    for (int s = 128; s; s >>= 1) {
        if (t < s) {
#pragma unroll
            for (int q = 0; q < 14; q++) red[q][t] += red[q][t + s];
        }
        __syncthreads();
    }
    if (t < 14) g_v6[t] = red[t][0];
}

// ---------------------------------------------------------------------------
// Features, feature-major per batch: g_feats[(b*8+q)*NN + s]
// ---------------------------------------------------------------------------
__global__ void feats_kernel(const float* __restrict__ arr, const float* __restrict__ dep,
                             const float* __restrict__ hard,
                             const float* __restrict__ ts, const float* __restrict__ tt)
{
    int row = blockIdx.x * 256 + threadIdx.x;
    int b = row >> 11;
    int s = row & (NN - 1);
    float t = ts[b], T = tt[b];
    float ar = arr[row], de = dep[row];
    float f[6];
    f[0] = (t - ar) / (de - ar);
    f[1] = t / T;
    f[2] = fmodf(f[1], 2.f);
    f[3] = fmodf(f[1], 4.f);
    f[4] = fmodf(f[1], 7.f);
    f[5] = hard[row];
    float* base = g_feats + (size_t)b * 8 * NN + s;
#pragma unroll
    for (int q = 0; q < 6; q++) base[q * NN] = f[q];
}

// ---------------------------------------------------------------------------
// Embedding from precomputed feats: x = feats @ Weff + beff (fp32 only)
// ---------------------------------------------------------------------------
__global__ void embed_kernel()
{
    int idx = blockIdx.x * 256 + threadIdx.x;
    int j = idx & (HH - 1);
    int row = idx >> 9;
    int b = row >> 11;
    int s = row & (NN - 1);
    const float* fb = g_feats + (size_t)b * 8 * NN + s;
    float acc = g_beff[j];
#pragma unroll
    for (int i = 0; i < 6; i++) acc += fb[i * NN] * g_Weff[i * HH + j];
    g_x[idx] = acc;
}

// ---------------------------------------------------------------------------
// Layer-0 e_src/e_dst via rank-6 + fused per-batch smax
// (each 256-row block lies entirely within one batch)
// ---------------------------------------------------------------------------
__global__ __launch_bounds__(256) void l0_e_kernel()
{
    int row = blockIdx.x * 256 + threadIdx.x;
    int b = row >> 11;
    int s = row & (NN - 1);
    const float* base = g_feats + (size_t)b * 8 * NN + s;
    float es = g_v6[12], ed = g_v6[13];
#pragma unroll
    for (int i = 0; i < 6; i++) {
        float fv = base[i * NN];
        es += fv * g_v6[i];
        ed += fv * g_v6[6 + i];
    }
    g_ee[row] = es;
    g_ee[MROWS + row] = ed;
    // fused per-batch max of esrc
    float v = es;
#pragma unroll
    for (int off = 16; off; off >>= 1)
        v = fmaxf(v, __shfl_xor_sync(0xFFFFFFFFu, v, off));
    __shared__ float red[8];
    const int w = threadIdx.x >> 5, l = threadIdx.x & 31;
    if (l == 0) red[w] = v;
    __syncthreads();
    if (threadIdx.x == 0) {
        float m = red[0];
#pragma unroll
        for (int q = 1; q < 8; q++) m = fmaxf(m, red[q]);
        atomicMax(&g_smax_bits[b], enc_ord(m));
    }
}

// ---------------------------------------------------------------------------
// Reset per-batch smax + zero ee
// ---------------------------------------------------------------------------
__global__ void zero_ee2_kernel()
{
    int i = blockIdx.x * 256 + threadIdx.x;
    if (i < 2 * MROWS) g_ee[i] = 0.f;
    if (i < NB) g_smax_bits[i] = 0x007FFFFFu;  // enc(-inf)
}

// ---------------------------------------------------------------------------
// Per-batch max of esrc -> g_smax_bits (L1/L2 after gemm0 fused dots)
// ---------------------------------------------------------------------------
__global__ __launch_bounds__(256) void smax_kernel()
{
    const int i = blockIdx.x * 256 + threadIdx.x;
    float v = g_ee[i];
#pragma unroll
    for (int off = 16; off; off >>= 1)
        v = fmaxf(v, __shfl_xor_sync(0xFFFFFFFFu, v, off));
    __shared__ float red[8];
    const int w = threadIdx.x >> 5, l = threadIdx.x & 31;
    if (l == 0) red[w] = v;
    __syncthreads();
    if (threadIdx.x == 0) {
        float m = red[0];
#pragma unroll
        for (int q = 1; q < 8; q++) m = fmaxf(m, red[q]);
        atomicMax(&g_smax_bits[i >> 11], enc_ord(m));
    }
}

// ---------------------------------------------------------------------------
// Per-node exp factors (all exponents <= 0 -> no overflow)
// ---------------------------------------------------------------------------
__global__ void nodeprep_kernel()
{
    int t = blockIdx.x * 256 + threadIdx.x;
    int b = t >> 11;
    float sm = dec_ord(g_smax_bits[b]);
    float es = g_ee[t], ed = g_ee[MROWS + t];
    g_f1[t] = __expf(es - sm);
    g_f2[t] = __expf(0.2f * (es - sm));
    float u = ed + sm;
    float mh = fmaxf(u, 0.2f * u);
    g_qa[t] = __expf(u - mh);
    g_qb[t] = __expf(0.2f * u - mh);
}

// ---------------------------------------------------------------------------
// L0 fused pgen: generate P row in registers, accumulate Z and P@feats.
// Feature-major smem [6][2048] -> conflict-free float4 loads.
// ---------------------------------------------------------------------------
__global__ __launch_bounds__(256) void pgen_l0_kernel()
{
    extern __shared__ float sf[];   // [6][2048] feats for this block's batch
    const int tid = threadIdx.x;
    const int wid = tid >> 5, lane = tid & 31;
    const int t = blockIdx.x * 8 + wid;
    const int b = t >> 11;
    {
        const float4* src = reinterpret_cast<const float4*>(g_feats + (size_t)b * 8 * NN);
        float4* dst = reinterpret_cast<float4*>(sf);
        for (int i = tid; i < 6 * NN / 4; i += 256) dst[i] = src[i];
    }
    __syncthreads();

    const float qa = g_qa[t], qb = g_qb[t];
    const uint32_t* wrow = g_adjT + (size_t)t * (NN / 32);
    const float* f1 = g_f1 + b * NN;
    const float* f2 = g_f2 + b * NN;
    float sum = 0.f;
    float c[6] = {0.f, 0.f, 0.f, 0.f, 0.f, 0.f};
#pragma unroll 2
    for (int i = 0; i < 16; i++) {
        const int s = i * 128 + lane * 4;
        const uint32_t w = wrow[s >> 5];
        const uint32_t sh = s & 31;
        float4 x1 = *reinterpret_cast<const float4*>(f1 + s);
        float4 x2 = *reinterpret_cast<const float4*>(f2 + s);
        float o0 = ((w >> (sh + 0)) & 1u) ? fmaxf(qa * x1.x, qb * x2.x) : 0.f;
        float o1 = ((w >> (sh + 1)) & 1u) ? fmaxf(qa * x1.y, qb * x2.y) : 0.f;
        float o2 = ((w >> (sh + 2)) & 1u) ? fmaxf(qa * x1.z, qb * x2.z) : 0.f;
        float o3 = ((w >> (sh + 3)) & 1u) ? fmaxf(qa * x1.w, qb * x2.w) : 0.f;
        sum += (o0 + o1) + (o2 + o3);
#pragma unroll
        for (int q = 0; q < 6; q++) {
            const float4 fq = *reinterpret_cast<const float4*>(sf + q * NN + s);
            c[q] += o0 * fq.x + o1 * fq.y + o2 * fq.z + o3 * fq.w;
        }
    }
#pragma unroll
    for (int off = 16; off; off >>= 1) {
        sum += __shfl_xor_sync(0xFFFFFFFFu, sum, off);
#pragma unroll
        for (int q = 0; q < 6; q++) c[q] += __shfl_xor_sync(0xFFFFFFFFu, c[q], off);
    }
    if (lane == 0) {
        const float rzv = 1.f / fmaxf(sum, 1e-30f);
        g_rz[t] = rzv;
        float* co = g_c6 + t * 8;
#pragma unroll
        for (int q = 0; q < 6; q++) co[q] = c[q] * rzv;
    }
}

// ---------------------------------------------------------------------------
// L0 output: hr[t][j] = h(relu( c6[t]·W0eff[:,j] + b0eff[j] ))
// ---------------------------------------------------------------------------
__global__ void l0_out_kernel()
{
    int idx = blockIdx.x * 256 + threadIdx.x;     // < MROWS*1024
    int j = idx & 1023;
    int row = idx >> 10;
    const float* c = g_c6 + row * 8;
    float acc = g_b0eff[j];
#pragma unroll
    for (int i = 0; i < 6; i++) acc += c[i] * g_W0eff[i * 1024 + j];
    g_hr[(size_t)row * 1024 + j] = __float2half_rn(fmaxf(acc, 0.f));
}

// ---------------------------------------------------------------------------
// Materialize P' (fp16) + fused row-sum -> g_rz (L1/L2). One warp per row.
// ---------------------------------------------------------------------------
__global__ __launch_bounds__(256) void pgen_kernel()
{
    const int wid = threadIdx.x >> 5, lane = threadIdx.x & 31;
    const int t = blockIdx.x * 8 + wid;
    const int b = t >> 11;
    const float qa = g_qa[t], qb = g_qb[t];
    const uint32_t* wrow = g_adjT + (size_t)t * (NN / 32);
    const float* f1 = g_f1 + b * NN;
    const float* f2 = g_f2 + b * NN;
    __half* Prow = g_P + (size_t)t * NN;
    float sum = 0.f;
#pragma unroll 4
    for (int i = 0; i < 16; i++) {
        const int s = i * 128 + lane * 4;
        const uint32_t w = wrow[s >> 5];
        const uint32_t sh = s & 31;
        float4 x1 = *reinterpret_cast<const float4*>(f1 + s);
        float4 x2 = *reinterpret_cast<const float4*>(f2 + s);
        float o0 = ((w >> (sh + 0)) & 1u) ? fmaxf(qa * x1.x, qb * x2.x) : 0.f;
        float o1 = ((w >> (sh + 1)) & 1u) ? fmaxf(qa * x1.y, qb * x2.y) : 0.f;
        float o2 = ((w >> (sh + 2)) & 1u) ? fmaxf(qa * x1.z, qb * x2.z) : 0.f;
        float o3 = ((w >> (sh + 3)) & 1u) ? fmaxf(qa * x1.w, qb * x2.w) : 0.f;
        __half2 p01 = __floats2half2_rn(o0, o1);
        __half2 p23 = __floats2half2_rn(o2, o3);
        float2 q01 = __half22float2(p01);
        float2 q23 = __half22float2(p23);
        sum += (q01.x + q01.y) + (q23.x + q23.y);
        *reinterpret_cast<__half2*>(Prow + s)     = p01;
        *reinterpret_cast<__half2*>(Prow + s + 2) = p23;
    }
#pragma unroll
    for (int off = 16; off; off >>= 1) sum += __shfl_xor_sync(0xFFFFFFFFu, sum, off);
    if (lane == 0) g_rz[t] = 1.f / fmaxf(sum, 1e-30f);
}

// ---------------------------------------------------------------------------
// Host launcher
// ---------------------------------------------------------------------------
extern "C" void kernel_launch(void* const* d_in, const int* in_sizes, int n_in,
                              void* d_out, int out_size)
{
    const int*   adj      = (const int*)d_in[0];
    const float* arrivals = (const float*)d_in[1];
    const float* depart   = (const float*)d_in[2];
    const float* hard     = (const float*)d_in[3];
    const float* active   = (const float*)d_in[4];
    const float* timestep = (const float*)d_in[5];
    const float* totalts  = (const float*)d_in[6];
    const float* embW1 = (const float*)d_in[7];
    const float* embb1 = (const float*)d_in[8];
    const float* embW2 = (const float*)d_in[9];
    const float* embb2 = (const float*)d_in[10];
    const float* gatW[3]    = {(const float*)d_in[11], (const float*)d_in[15], (const float*)d_in[19]};
    const float* gatAsrc[3] = {(const float*)d_in[12], (const float*)d_in[16], (const float*)d_in[20]};
    const float* gatAdst[3] = {(const float*)d_in[13], (const float*)d_in[17], (const float*)d_in[21]};
    const float* gatB[3]    = {(const float*)d_in[14], (const float*)d_in[18], (const float*)d_in[22]};
    const float* ffW1 = (const float*)d_in[23];
    const float* ffb1 = (const float*)d_in[24];
    const float* ffW2 = (const float*)d_in[25];
    const float* ffb2 = (const float*)d_in[26];

    float *x, *h, *rz, *ee;
    __half *xr, *hr, *hwt, *P, *wt;
    cudaGetSymbolAddress((void**)&x,   g_x);
    cudaGetSymbolAddress((void**)&xr,  g_xr);
    cudaGetSymbolAddress((void**)&h,   g_h);
    cudaGetSymbolAddress((void**)&hr,  g_hr);
    cudaGetSymbolAddress((void**)&hwt, g_hwt);
    cudaGetSymbolAddress((void**)&P,   g_P);
    cudaGetSymbolAddress((void**)&rz,  g_rz);
    cudaGetSymbolAddress((void**)&wt,  g_wt);
    cudaGetSymbolAddress((void**)&ee,  g_ee);

    static int smem_set = 0;
    if (!smem_set) {
        cudaFuncSetAttribute(gemm_tc<0>, cudaFuncAttributeMaxDynamicSharedMemorySize, SMEM_BYTES);
        cudaFuncSetAttribute(gemm_tc<1>, cudaFuncAttributeMaxDynamicSharedMemorySize, SMEM_BYTES);
        cudaFuncSetAttribute(gemm_tc<2>, cudaFuncAttributeMaxDynamicSharedMemorySize, SMEM_BYTES);
        cudaFuncSetAttribute(gemm_tc<3>, cudaFuncAttributeMaxDynamicSharedMemorySize, SMEM_BYTES);
        cudaFuncSetAttribute(gemm_tc<4>, cudaFuncAttributeMaxDynamicSharedMemorySize, SMEM_BYTES);
        cudaFuncSetAttribute(pgen_l0_kernel, cudaFuncAttributeMaxDynamicSharedMemorySize, 6 * NN * 4);
        smem_set = 1;
    }

    // Prep + features + embedding + adjacency
    prep_weff_kernel<<<2, 256>>>(embW1, embb1, embW2, embb2);
    feats_kernel<<<MROWS / 256, 256>>>(arrivals, depart, hard, timestep, totalts);
    prep_l0a_part<<<dim3(4, 8), 256>>>(gatW[0]);
    prep_l0a_red<<<28, 256>>>(gatB[0]);
    prep_l0b_kernel<<<1, 256>>>(gatAsrc[0], gatAdst[0]);
    embed_kernel<<<(MROWS * HH) / 256, 256>>>();
    adjT_kernel<<<dim3(NN / 32, NN / 32, NB), 1024>>>(adj);

    // ---- Layer 0: rank-6 collapsed attention ----
    zero_ee2_kernel<<<(2 * MROWS) / 256, 256>>>();   // resets smax
    l0_e_kernel<<<MROWS / 256, 256>>>();             // e + fused smax
    nodeprep_kernel<<<MROWS / 256, 256>>>();
    pgen_l0_kernel<<<MROWS / 8, 256, 6 * NN * 4>>>();
    l0_out_kernel<<<(MROWS * 1024) / 256, 256>>>();

    // ---- Layers 1, 2: dense path ----
    const int Kin[3] = {0, 1024, 1024};
    const int Fo[3]  = {0, 1024, HH};
    const dim3 tblk(32, 8);
    for (int l = 1; l < 3; l++) {
        transpose_kernel<<<dim3(Fo[l] / 32, Kin[l] / 32), tblk>>>(gatW[l], wt, Kin[l], Fo[l]);
        zero_ee2_kernel<<<(2 * MROWS) / 256, 256>>>();
        gemm_tc<0><<<dim3(Fo[l] / 128, MROWS / 128), 256, SMEM_BYTES>>>(
            hr, wt, nullptr, hwt, Kin[l], Fo[l], gatAsrc[l], gatAdst[l], nullptr, nullptr, ee);
        smax_kernel<<<MROWS / 256, 256>>>();
        nodeprep_kernel<<<MROWS / 256, 256>>>();
        pgen_kernel<<<MROWS / 8, 256>>>();
        if (l < 2) {
            gemm_tc<1><<<dim3(Fo[l] / 128, NN / 128, NB), 256, SMEM_BYTES>>>(
                P, hwt, nullptr, hr, NN, Fo[l], gatB[l], nullptr, nullptr, rz, nullptr);
        } else {
            gemm_tc<2><<<dim3(Fo[l] / 128, NN / 128, NB), 256, SMEM_BYTES>>>(
                P, hwt, h, hr, NN, Fo[l], gatB[l], x, nullptr, rz, nullptr);
        }
    }

    // ff1: x2 = x1 + relu(x1 @ W1 + b1)
    transpose_kernel<<<dim3(HH / 32, HH / 32), tblk>>>(ffW1, wt, HH, HH);
    gemm_tc<3><<<dim3(HH / 128, MROWS / 128), 256, SMEM_BYTES>>>(
        hr, wt, x, xr, HH, HH, ffb1, h, nullptr, nullptr, nullptr);
    // ff2: out = (x2 + relu(x2 @ W2 + b2)) * active
    transpose_kernel<<<dim3(HH / 32, HH / 32), tblk>>>(ffW2, wt, HH, HH);
    gemm_tc<4><<<dim3(HH / 128, MROWS / 128), 256, SMEM_BYTES>>>(
        xr, wt, (float*)d_out, nullptr, HH, HH, ffb2, x, active, nullptr, nullptr);
}